// round 6
// baseline (speedup 1.0000x reference)
#include <cuda_runtime.h>
#include <math.h>
#include <float.h>

#define BS 64
#define SEQ 128
#define IN_DIM 256
#define H 512
#define NSLOT 4096
#define MDIM 128
#define RHEADS 4
#define OUTD 64
#define GAMMA_F 0.95f
#define JH (4 * H)               /* 2048 */
#define QW (RHEADS * MDIM)       /* 512  */
#define OUTW (H + RHEADS * MDIM) /* 1024 */
#define KSPL 8
#define RVCH 16

/* ------------------- persistent device state -------------------------------- */
__device__ float g_mem[(size_t)BS * NSLOT * MDIM];
__device__ float g_rw[BS * RHEADS * NSLOT];
__device__ float g_uw[BS * NSLOT];
__device__ float g_h[BS * H];
__device__ float g_c[BS * H];
__device__ float g_zx[(size_t)SEQ * BS * JH];
__device__ float g_zpart[KSPL * BS * JH];
__device__ float g_qpart[KSPL * BS * QW];
__device__ float g_qall[(size_t)SEQ * BS * QW];
__device__ int   g_idx[BS * RHEADS];
__device__ float g_alpha_s[BS * RHEADS];
__device__ float g_logits[BS * RHEADS * NSLOT];
__device__ float g_lmax[BS * RVCH * RHEADS];
__device__ float g_wwsum[BS * NSLOT];
__device__ float g_hist_h[(size_t)SEQ * BS * H];
__device__ float g_rvpart[(size_t)SEQ * RVCH * BS * QW];
__device__ float g_normQb[BS];
__device__ float g_normM_part[BS * 16];

__device__ __forceinline__ float sigmoidf_(float v) { return 1.f / (1.f + expf(-v)); }

/* ------------------- init ---------------------------------------------------- */
__global__ void k_init(const float* __restrict__ alpha) {
    int i = blockIdx.x * 256 + threadIdx.x;
    if (i < BS * H) { g_h[i] = 0.f; g_c[i] = 0.f; }
    if (i < BS * RHEADS) g_alpha_s[i] = sigmoidf_(alpha[i]);
}

/* ------------------- zx precompute ------------------------------------------ */
__global__ void k_zx(const float* __restrict__ x, const float* __restrict__ y,
                     const float* __restrict__ Wl, const float* __restrict__ bl, int t0) {
    __shared__ float s_in[16][68];
    int tid = threadIdx.x;
    int tj = tid & 15, tb = tid >> 4;
    int j0 = blockIdx.x * 64;
    int t  = blockIdx.y + t0;
    float acc[4][4];
#pragma unroll
    for (int i = 0; i < 4; i++)
#pragma unroll
        for (int jj = 0; jj < 4; jj++) acc[i][jj] = 0.f;

    for (int k0 = 0; k0 < IN_DIM; k0 += 16) {
        for (int l = tid; l < 1024; l += 256) {
            int kk = l & 15, b = l >> 4;
            s_in[kk][b] = x[((size_t)b * SEQ + t) * IN_DIM + k0 + kk];
        }
        __syncthreads();
#pragma unroll 4
        for (int kk = 0; kk < 16; kk++) {
            float4 av = *reinterpret_cast<const float4*>(&s_in[kk][tb * 4]);
            float4 wv = *reinterpret_cast<const float4*>(&Wl[(size_t)(k0 + kk) * JH + j0 + tj * 4]);
            const float* a = (const float*)&av;
            const float* w = (const float*)&wv;
#pragma unroll
            for (int bi = 0; bi < 4; bi++)
#pragma unroll
                for (int ji = 0; ji < 4; ji++) acc[bi][ji] += a[bi] * w[ji];
        }
        __syncthreads();
    }
    float4 bv = *reinterpret_cast<const float4*>(&bl[j0 + tj * 4]);
    float4 wy = *reinterpret_cast<const float4*>(&Wl[(size_t)IN_DIM * JH + j0 + tj * 4]);
    const float* bb = (const float*)&bv;
    const float* wyp = (const float*)&wy;
#pragma unroll
    for (int bi = 0; bi < 4; bi++) {
        int b = tb * 4 + bi;
        float yb = (t > 0) ? y[b * SEQ + t - 1] : 0.f;
        float4 o;
        o.x = acc[bi][0] + bb[0] + yb * wyp[0];
        o.y = acc[bi][1] + bb[1] + yb * wyp[1];
        o.z = acc[bi][2] + bb[2] + yb * wyp[2];
        o.w = acc[bi][3] + bb[3] + yb * wyp[3];
        *reinterpret_cast<float4*>(&g_zx[((size_t)t * BS + b) * JH + j0 + tj * 4]) = o;
    }
}

/* ------------------- recurrent GEMM partial --------------------------------- */
__global__ void k_rec(const float* __restrict__ Wl) {
    __shared__ float s_in[16][68];
    int tid = threadIdx.x;
    int tj = tid & 15, tb = tid >> 4;
    int j0 = blockIdx.x * 64;
    int s  = blockIdx.y;
    int kbase = s * (H / KSPL);
    float acc[4][4];
#pragma unroll
    for (int i = 0; i < 4; i++)
#pragma unroll
        for (int jj = 0; jj < 4; jj++) acc[i][jj] = 0.f;

    for (int k0 = 0; k0 < H / KSPL; k0 += 16) {
        for (int l = tid; l < 1024; l += 256) {
            int kk = l & 15, b = l >> 4;
            s_in[kk][b] = g_h[b * H + kbase + k0 + kk];
        }
        __syncthreads();
#pragma unroll 4
        for (int kk = 0; kk < 16; kk++) {
            float4 av = *reinterpret_cast<const float4*>(&s_in[kk][tb * 4]);
            float4 wv = *reinterpret_cast<const float4*>(
                &Wl[(size_t)(IN_DIM + 1 + kbase + k0 + kk) * JH + j0 + tj * 4]);
            const float* a = (const float*)&av;
            const float* w = (const float*)&wv;
#pragma unroll
            for (int bi = 0; bi < 4; bi++)
#pragma unroll
                for (int ji = 0; ji < 4; ji++) acc[bi][ji] += a[bi] * w[ji];
        }
        __syncthreads();
    }
#pragma unroll
    for (int bi = 0; bi < 4; bi++) {
        int b = tb * 4 + bi;
        float4 o;
        o.x = acc[bi][0]; o.y = acc[bi][1]; o.z = acc[bi][2]; o.w = acc[bi][3];
        *reinterpret_cast<float4*>(&g_zpart[((size_t)s * BS + b) * JH + j0 + tj * 4]) = o;
    }
}

/* ------------------- gates --------------------------------------------------- */
__global__ void k_gates(int t) {
    int i = blockIdx.x * 256 + threadIdx.x;
    if (i >= BS * H) return;
    int b = i / H, hh = i % H;
    size_t zbase = ((size_t)t * BS + b) * JH;
    float zg[4];
#pragma unroll
    for (int g = 0; g < 4; g++) {
        float v = g_zx[zbase + g * H + hh];
#pragma unroll
        for (int s = 0; s < KSPL; s++)
            v += g_zpart[((size_t)s * BS + b) * JH + g * H + hh];
        zg[g] = v;
    }
    float f  = sigmoidf_(zg[0]);
    float ig = sigmoidf_(zg[1]);
    float o  = sigmoidf_(zg[2]);
    float u  = tanhf(zg[3]);
    float c  = f * g_c[i] + ig * u;
    float h  = o * tanhf(c);
    g_c[i] = c; g_h[i] = h;
    g_hist_h[((size_t)t * BS + b) * H + hh] = h;
}

/* ------------------- query GEMM partial -------------------------------------- */
__global__ void k_query(const float* __restrict__ Wm) {
    __shared__ float s_in[16][68];
    int tid = threadIdx.x;
    int tj = tid & 15, tb = tid >> 4;
    int j0 = blockIdx.x * 64;
    int s  = blockIdx.y;
    int kbase = s * (H / KSPL);
    float acc[4][4];
#pragma unroll
    for (int i = 0; i < 4; i++)
#pragma unroll
        for (int jj = 0; jj < 4; jj++) acc[i][jj] = 0.f;

    for (int k0 = 0; k0 < H / KSPL; k0 += 16) {
        for (int l = tid; l < 1024; l += 256) {
            int kk = l & 15, b = l >> 4;
            s_in[kk][b] = g_h[b * H + kbase + k0 + kk];
        }
        __syncthreads();
#pragma unroll 4
        for (int kk = 0; kk < 16; kk++) {
            float4 av = *reinterpret_cast<const float4*>(&s_in[kk][tb * 4]);
            float4 wv = *reinterpret_cast<const float4*>(
                &Wm[(size_t)(kbase + k0 + kk) * QW + j0 + tj * 4]);
            const float* a = (const float*)&av;
            const float* w = (const float*)&wv;
#pragma unroll
            for (int bi = 0; bi < 4; bi++)
#pragma unroll
                for (int ji = 0; ji < 4; ji++) acc[bi][ji] += a[bi] * w[ji];
        }
        __syncthreads();
    }
#pragma unroll
    for (int bi = 0; bi < 4; bi++) {
        int b = tb * 4 + bi;
        float4 o;
        o.x = acc[bi][0]; o.y = acc[bi][1]; o.z = acc[bi][2]; o.w = acc[bi][3];
        *reinterpret_cast<float4*>(&g_qpart[((size_t)s * BS + b) * QW + j0 + tj * 4]) = o;
    }
}

/* ------------------- combine q partials -------------------------------------- */
__global__ void k_qcomb(const float* __restrict__ bm, int t) {
    int l = blockIdx.x * 256 + threadIdx.x;
    if (l >= BS * QW) return;
    int b = l >> 9, j = l & 511;
    float v = bm[j];
#pragma unroll
    for (int s = 0; s < KSPL; s++) v += g_qpart[((size_t)s * BS + b) * QW + j];
    g_qall[((size_t)t * BS + b) * QW + j] = v;
}

/* ------------------- initial select ------------------------------------------ */
__global__ void k_select0() {
    int b = blockIdx.x;
    int tid = threadIdx.x;
    __shared__ float sv[256];
    __shared__ int   si[256];
    __shared__ int   picked[RHEADS];
    const float* uw = &g_uw[(size_t)b * NSLOT];
    for (int r = 0; r < RHEADS; r++) {
        float bestv = FLT_MAX;
        int besti = 0x7fffffff;
        for (int n = tid; n < NSLOT; n += 256) {
            bool skip = false;
            for (int p = 0; p < r; p++) if (picked[p] == n) skip = true;
            if (skip) continue;
            float v = uw[n];
            if (v < bestv || (v == bestv && n < besti)) { bestv = v; besti = n; }
        }
        sv[tid] = bestv; si[tid] = besti;
        __syncthreads();
        for (int s = 128; s > 0; s >>= 1) {
            if (tid < s) {
                if (sv[tid + s] < sv[tid] || (sv[tid + s] == sv[tid] && si[tid + s] < si[tid])) {
                    sv[tid] = sv[tid + s]; si[tid] = si[tid + s];
                }
            }
            __syncthreads();
        }
        if (tid == 0) { picked[r] = si[0]; g_idx[b * RHEADS + r] = si[0]; }
        __syncthreads();
    }
}

/* ------------------- memupd(t): update+logits+maxes+norms+readvec(t-1) ------- */
__global__ void k_memupd(int t) {
    int b  = blockIdx.y;
    int n0 = blockIdx.x * 256;
    __shared__ float sq[RHEADS][MDIM];
    __shared__ float srw[RHEADS][256];
    __shared__ float sal[RHEADS];
    __shared__ int   sidx[RHEADS];
    __shared__ float sredn[8];
    __shared__ float smax[8][RHEADS];
    __shared__ float s_red[256];
    __shared__ float sacc[8][QW];
    int tid = threadIdx.x;

    for (int l = tid; l < QW; l += 256)
        sq[l >> 7][l & 127] = g_qall[((size_t)t * BS + b) * QW + l];
    for (int l = tid; l < RHEADS * 256; l += 256) {
        int r = l >> 8, nn = l & 255;
        srw[r][nn] = g_rw[((size_t)b * RHEADS + r) * NSLOT + n0 + nn];
    }
    if (tid < RHEADS) { sal[tid] = g_alpha_s[b * RHEADS + tid]; sidx[tid] = g_idx[b * RHEADS + tid]; }
    __syncthreads();

    if (blockIdx.x == 0) {
        float local = 0.f;
        for (int l = tid; l < QW; l += 256) {
            float v = sq[l >> 7][l & 127];
            local += v * v;
        }
        s_red[tid] = local;
        __syncthreads();
        for (int s = 128; s > 0; s >>= 1) {
            if (tid < s) s_red[tid] += s_red[tid + s];
            __syncthreads();
        }
        if (tid == 0) g_normQb[b] = s_red[0];
        __syncthreads();
    }

    int warp = tid >> 5, lane = tid & 31;
    float normp = 0.f;
    float m0 = -FLT_MAX, m1 = -FLT_MAX, m2 = -FLT_MAX, m3 = -FLT_MAX;
    float rva[RHEADS][4];
#pragma unroll
    for (int r = 0; r < RHEADS; r++)
#pragma unroll
        for (int c = 0; c < 4; c++) rva[r][c] = 0.f;

#pragma unroll 2
    for (int row = warp; row < 256; row += 8) {
        int n = n0 + row;
        float r0w = srw[0][row], r1w = srw[1][row], r2w = srw[2][row], r3w = srw[3][row];
        float w0 = sal[0] * r0w; if (n == sidx[0]) w0 += 1.f - sal[0];
        float w1 = sal[1] * r1w; if (n == sidx[1]) w1 += 1.f - sal[1];
        float w2 = sal[2] * r2w; if (n == sidx[2]) w2 += 1.f - sal[2];
        float w3 = sal[3] * r3w; if (n == sidx[3]) w3 += 1.f - sal[3];
        float* mp = &g_mem[((size_t)b * NSLOT + n) * MDIM + lane * 4];
        float4 v = *reinterpret_cast<float4*>(mp);
        float* vv = (float*)&v;
        float d0 = 0.f, d1 = 0.f, d2 = 0.f, d3 = 0.f;
#pragma unroll
        for (int cpt = 0; cpt < 4; cpt++) {
            int m = lane * 4 + cpt;
            float pre = vv[cpt];
            rva[0][cpt] += r0w * pre; rva[1][cpt] += r1w * pre;
            rva[2][cpt] += r2w * pre; rva[3][cpt] += r3w * pre;
            float q0 = sq[0][m], q1 = sq[1][m], q2 = sq[2][m], q3 = sq[3][m];
            float nv = pre + w0 * q0 + w1 * q1 + w2 * q2 + w3 * q3;
            d0 += q0 * nv; d1 += q1 * nv; d2 += q2 * nv; d3 += q3 * nv;
            normp += nv * nv;
            vv[cpt] = nv;
        }
        *reinterpret_cast<float4*>(mp) = v;
#pragma unroll
        for (int off = 16; off > 0; off >>= 1) {
            d0 += __shfl_down_sync(0xffffffffu, d0, off);
            d1 += __shfl_down_sync(0xffffffffu, d1, off);
            d2 += __shfl_down_sync(0xffffffffu, d2, off);
            d3 += __shfl_down_sync(0xffffffffu, d3, off);
        }
        if (lane == 0) {
            g_logits[((size_t)b * RHEADS + 0) * NSLOT + n] = d0;
            g_logits[((size_t)b * RHEADS + 1) * NSLOT + n] = d1;
            g_logits[((size_t)b * RHEADS + 2) * NSLOT + n] = d2;
            g_logits[((size_t)b * RHEADS + 3) * NSLOT + n] = d3;
            g_wwsum[(size_t)b * NSLOT + n] = w0 + w1 + w2 + w3;
            m0 = fmaxf(m0, d0); m1 = fmaxf(m1, d1);
            m2 = fmaxf(m2, d2); m3 = fmaxf(m3, d3);
        }
    }
#pragma unroll
    for (int off = 16; off > 0; off >>= 1) normp += __shfl_down_sync(0xffffffffu, normp, off);
    if (lane == 0) {
        sredn[warp] = normp;
        smax[warp][0] = m0; smax[warp][1] = m1; smax[warp][2] = m2; smax[warp][3] = m3;
    }

#pragma unroll
    for (int r = 0; r < RHEADS; r++)
#pragma unroll
        for (int c = 0; c < 4; c++) sacc[warp][r * MDIM + lane * 4 + c] = rva[r][c];
    __syncthreads();

    if (tid == 0) {
        float s = 0.f;
        for (int i = 0; i < 8; i++) s += sredn[i];
        g_normM_part[b * 16 + blockIdx.x] = s;
    }
    if (tid < RHEADS) {
        float mm = smax[0][tid];
#pragma unroll
        for (int w = 1; w < 8; w++) mm = fmaxf(mm, smax[w][tid]);
        g_lmax[((size_t)b * RVCH + blockIdx.x) * RHEADS + tid] = mm;
    }
    if (t > 0) {
        for (int l = tid; l < QW; l += 256) {
            float s = 0.f;
#pragma unroll
            for (int w = 0; w < 8; w++) s += sacc[w][l];
            g_rvpart[(((size_t)(t - 1) * RVCH + blockIdx.x) * BS + b) * QW + l] = s;
        }
    }
}

/* ------------------- exp/normalize: one head per block ----------------------- */
/* grid (RHEADS, BS), 256 threads                                                */
__global__ void k_expw() {
    int g = blockIdx.x, b = blockIdx.y;
    int tid = threadIdx.x;
    __shared__ float red[256];
    __shared__ float s_invscale;

    /* global norms (redundant per block; parallel hardware) */
    float v = g_normM_part[tid] + g_normM_part[tid + 256] +
              g_normM_part[tid + 512] + g_normM_part[tid + 768];
    red[tid] = v;
    __syncthreads();
    for (int s = 128; s > 0; s >>= 1) {
        if (tid < s) red[tid] += red[tid + s];
        __syncthreads();
    }
    float nm = red[0];
    __syncthreads();
    red[tid] = (tid < BS) ? g_normQb[tid] : 0.f;
    __syncthreads();
    for (int s = 128; s > 0; s >>= 1) {
        if (tid < s) red[tid] += red[tid + s];
        __syncthreads();
    }
    if (tid == 0) s_invscale = 1.f / (sqrtf(red[0]) * sqrtf(nm));
    __syncthreads();
    float invs = s_invscale;

    const float* lg = &g_logits[((size_t)b * RHEADS + g) * NSLOT];
    float* rw = &g_rw[((size_t)b * RHEADS + g) * NSLOT];

    float mxr = -FLT_MAX;
#pragma unroll
    for (int ch = 0; ch < RVCH; ch++)
        mxr = fmaxf(mxr, g_lmax[((size_t)b * RVCH + ch) * RHEADS + g]);
    float mx = mxr * invs;

    float e[16];
    float sum = 0.f;
#pragma unroll
    for (int i = 0; i < 16; i++) {
        float t = expf(lg[tid + i * 256] * invs - mx);
        e[i] = t; sum += t;
    }
    red[tid] = sum;
    __syncthreads();
    for (int s = 128; s > 0; s >>= 1) {
        if (tid < s) red[tid] += red[tid + s];
        __syncthreads();
    }
    float inv = 1.f / red[0];
#pragma unroll
    for (int i = 0; i < 16; i++) rw[tid + i * 256] = e[i] * inv;
}

/* ------------------- uw update + single-pass top-4 select -------------------- */
/* grid BS, 512 threads                                                           */
__global__ void k_uwsel() {
    int b = blockIdx.x, tid = threadIdx.x;
    __shared__ float suw[NSLOT];
    __shared__ float s4v[512][4];
    __shared__ int   s4i[512][4];

    for (int n = tid; n < NSLOT; n += 512) {
        size_t base = (size_t)b * RHEADS * NSLOT;
        float rs = g_rw[base + n] + g_rw[base + NSLOT + n] +
                   g_rw[base + 2 * NSLOT + n] + g_rw[base + 3 * NSLOT + n];
        size_t ui = (size_t)b * NSLOT + n;
        float u = GAMMA_F * g_uw[ui] + rs + g_wwsum[ui];
        g_uw[ui] = u;
        suw[n] = u;
    }
    __syncthreads();

    /* per-thread sorted top-4 (ascending by (v, idx)) */
    float tv[4]; int ti[4];
#pragma unroll
    for (int k = 0; k < 4; k++) { tv[k] = FLT_MAX; ti[k] = 0x7fffffff; }
    for (int n = tid; n < NSLOT; n += 512) {
        float v = suw[n];
        if (v < tv[3] || (v == tv[3] && n < ti[3])) {
            int k = 3;
            while (k > 0 && (v < tv[k - 1] || (v == tv[k - 1] && n < ti[k - 1]))) {
                tv[k] = tv[k - 1]; ti[k] = ti[k - 1]; k--;
            }
            tv[k] = v; ti[k] = n;
        }
    }
#pragma unroll
    for (int k = 0; k < 4; k++) { s4v[tid][k] = tv[k]; s4i[tid][k] = ti[k]; }
    __syncthreads();

    /* tree merge of top-4 lists */
    for (int s = 256; s > 0; s >>= 1) {
        if (tid < s) {
            float av[4], bv[4], ov[4];
            int ai[4], bi[4], oi[4];
#pragma unroll
            for (int k = 0; k < 4; k++) {
                av[k] = s4v[tid][k];     ai[k] = s4i[tid][k];
                bv[k] = s4v[tid + s][k]; bi[k] = s4i[tid + s][k];
            }
            int a = 0, c = 0;
#pragma unroll
            for (int k = 0; k < 4; k++) {
                bool takeA = (av[a] < bv[c]) || (av[a] == bv[c] && ai[a] < bi[c]);
                if (takeA) { ov[k] = av[a]; oi[k] = ai[a]; a++; }
                else       { ov[k] = bv[c]; oi[k] = bi[c]; c++; }
            }
#pragma unroll
            for (int k = 0; k < 4; k++) { s4v[tid][k] = ov[k]; s4i[tid][k] = oi[k]; }
        }
        __syncthreads();
    }
    if (tid < RHEADS) g_idx[b * RHEADS + tid] = s4i[0][tid];
}

/* ------------------- final mem copy-out + readvec(SEQ-1) --------------------- */
__global__ void k_memcopy_rv(float* __restrict__ out_mem) {
    int b  = blockIdx.y;
    int n0 = blockIdx.x * 256;
    int tid = threadIdx.x;
    int warp = tid >> 5, lane = tid & 31;
    __shared__ float srw[RHEADS][256];
    __shared__ float sacc[8][QW];

    for (int l = tid; l < RHEADS * 256; l += 256) {
        int r = l >> 8, nn = l & 255;
        srw[r][nn] = g_rw[((size_t)b * RHEADS + r) * NSLOT + n0 + nn];
    }
    __syncthreads();

    float rva[RHEADS][4];
#pragma unroll
    for (int r = 0; r < RHEADS; r++)
#pragma unroll
        for (int c = 0; c < 4; c++) rva[r][c] = 0.f;

    for (int row = warp; row < 256; row += 8) {
        int n = n0 + row;
        size_t off = ((size_t)b * NSLOT + n) * MDIM + lane * 4;
        float4 v = *reinterpret_cast<const float4*>(&g_mem[off]);
        *reinterpret_cast<float4*>(&out_mem[off]) = v;
        const float* vv = (const float*)&v;
#pragma unroll
        for (int r = 0; r < RHEADS; r++) {
            float w = srw[r][row];
#pragma unroll
            for (int c = 0; c < 4; c++) rva[r][c] += w * vv[c];
        }
    }
#pragma unroll
    for (int r = 0; r < RHEADS; r++)
#pragma unroll
        for (int c = 0; c < 4; c++) sacc[warp][r * MDIM + lane * 4 + c] = rva[r][c];
    __syncthreads();
    for (int l = tid; l < QW; l += 256) {
        float s = 0.f;
#pragma unroll
        for (int w = 0; w < 8; w++) s += sacc[w][l];
        g_rvpart[(((size_t)(SEQ - 1) * RVCH + blockIdx.x) * BS + b) * QW + l] = s;
    }
}

/* ------------------- final projection + softmax ------------------------------ */
__global__ void k_final(const float* __restrict__ Wf, const float* __restrict__ bf,
                        float* __restrict__ out) {
    extern __shared__ float sm[];
    float (*svv)[OUTW] = (float (*)[OUTW])sm;
    float* red = sm + 16 * OUTW;
    int tid = threadIdx.x;
    int r0 = blockIdx.x * 16;
    int t  = r0 / BS;
    int b0 = r0 % BS;

    for (int l = tid; l < 16 * H; l += 128) {
        int rr = l >> 9, k = l & 511;
        svv[rr][k] = g_hist_h[((size_t)(r0 + rr)) * H + k];
    }
    for (int l = tid; l < 16 * QW; l += 128) {
        int rr = l >> 9, k = l & 511;
        float s = 0.f;
#pragma unroll
        for (int c = 0; c < RVCH; c++)
            s += g_rvpart[(((size_t)t * RVCH + c) * BS + (b0 + rr)) * QW + k];
        svv[rr][H + k] = s;
    }
    __syncthreads();

    int half = tid >> 6, col = tid & 63;
    float accs[8];
#pragma unroll
    for (int rr = 0; rr < 8; rr++) accs[rr] = bf[col];
    for (int k = 0; k < OUTW; k++) {
        float w = Wf[(size_t)k * OUTD + col];
#pragma unroll
        for (int rr = 0; rr < 8; rr++) accs[rr] += svv[half * 8 + rr][k] * w;
    }
    for (int rr = 0; rr < 8; rr++) {
        red[tid] = accs[rr];
        __syncthreads();
        for (int s = 32; s > 0; s >>= 1) {
            if ((tid & 63) < s) red[tid] = fmaxf(red[tid], red[tid + s]);
            __syncthreads();
        }
        float mx = red[half * 64];
        __syncthreads();
        float e = expf(accs[rr] - mx);
        red[tid] = e;
        __syncthreads();
        for (int s = 32; s > 0; s >>= 1) {
            if ((tid & 63) < s) red[tid] += red[tid + s];
            __syncthreads();
        }
        float denom = red[half * 64];
        __syncthreads();
        int b = b0 + half * 8 + rr;
        out[((size_t)b * SEQ + t) * OUTD + col] = e / denom;
    }
}

/* ------------------- host: two-stream fork/join pipeline --------------------- */
extern "C" void kernel_launch(void* const* d_in, const int* in_sizes, int n_in,
                              void* d_out, int out_size) {
    const float* x            = (const float*)d_in[0];
    const float* y            = (const float*)d_in[1];
    const float* memory       = (const float*)d_in[2];
    const float* read_weight  = (const float*)d_in[3];
    const float* usage_weight = (const float*)d_in[4];
    const float* Wl           = (const float*)d_in[5];
    const float* bl           = (const float*)d_in[6];
    const float* Wm           = (const float*)d_in[7];
    const float* bm           = (const float*)d_in[8];
    const float* Wf           = (const float*)d_in[9];
    const float* bf           = (const float*)d_in[10];
    const float* alpha        = (const float*)d_in[11];
    float* out = (float*)d_out;

    static cudaStream_t s1;
    static cudaEvent_t evFork, evJoin, evQ[SEQ];
    static int inited = 0;
    if (!inited) {
        cudaStreamCreateWithFlags(&s1, cudaStreamNonBlocking);
        cudaEventCreateWithFlags(&evFork, cudaEventDisableTiming);
        cudaEventCreateWithFlags(&evJoin, cudaEventDisableTiming);
        for (int t = 0; t < SEQ; t++)
            cudaEventCreateWithFlags(&evQ[t], cudaEventDisableTiming);
        cudaFuncSetAttribute(k_final, cudaFuncAttributeMaxDynamicSharedMemorySize,
                             (16 * OUTW + 128) * (int)sizeof(float));
        inited = 1;
    }

    cudaMemcpyToSymbolAsync(g_mem, memory, sizeof(float) * (size_t)BS * NSLOT * MDIM, 0,
                            cudaMemcpyDeviceToDevice, 0);
    cudaMemcpyToSymbolAsync(g_rw, read_weight, sizeof(float) * BS * RHEADS * NSLOT, 0,
                            cudaMemcpyDeviceToDevice, 0);
    cudaMemcpyToSymbolAsync(g_uw, usage_weight, sizeof(float) * BS * NSLOT, 0,
                            cudaMemcpyDeviceToDevice, 0);
    k_init<<<(BS * H + 255) / 256, 256>>>(alpha);
    k_select0<<<BS, 256>>>();

    cudaEventRecord(evFork, 0);
    cudaStreamWaitEvent(s1, evFork, 0);

    /* controller chain on s1 */
    k_zx<<<dim3(32, 1), 256, 0, s1>>>(x, y, Wl, bl, 0);
    k_rec<<<dim3(32, KSPL), 256, 0, s1>>>(Wl);
    k_gates<<<(BS * H) / 256, 256, 0, s1>>>(0);
    k_query<<<dim3(8, KSPL), 256, 0, s1>>>(Wm);
    k_qcomb<<<(BS * QW + 255) / 256, 256, 0, s1>>>(bm, 0);
    cudaEventRecord(evQ[0], s1);
    k_zx<<<dim3(32, SEQ - 1), 256, 0, s1>>>(x, y, Wl, bl, 1);
    for (int t = 1; t < SEQ; t++) {
        k_rec<<<dim3(32, KSPL), 256, 0, s1>>>(Wl);
        k_gates<<<(BS * H) / 256, 256, 0, s1>>>(t);
        k_query<<<dim3(8, KSPL), 256, 0, s1>>>(Wm);
        k_qcomb<<<(BS * QW + 255) / 256, 256, 0, s1>>>(bm, t);
        cudaEventRecord(evQ[t], s1);
    }
    cudaEventRecord(evJoin, s1);

    /* memory chain on capture stream */
    for (int t = 0; t < SEQ; t++) {
        cudaStreamWaitEvent(0, evQ[t], 0);
        k_memupd<<<dim3(16, BS), 256>>>(t);
        k_expw<<<dim3(RHEADS, BS), 256>>>();
        k_uwsel<<<BS, 512>>>();
    }
    cudaStreamWaitEvent(0, evJoin, 0);

    size_t np = (size_t)BS * SEQ * OUTD;
    size_t nm = (size_t)BS * NSLOT * MDIM;
    size_t nr = (size_t)BS * RHEADS * NSLOT;
    k_memcopy_rv<<<dim3(16, BS), 256>>>(out + np);
    cudaMemcpyFromSymbolAsync(out + np + nm, g_rw, nr * sizeof(float), 0,
                              cudaMemcpyDeviceToDevice, 0);
    cudaMemcpyFromSymbolAsync(out + np + nm + nr, g_uw, (size_t)BS * NSLOT * sizeof(float), 0,
                              cudaMemcpyDeviceToDevice, 0);
    k_final<<<SEQ * BS / 16, 128, (16 * OUTW + 128) * sizeof(float)>>>(Wf, bf, out);
}

// round 7
// speedup vs baseline: 1.1681x; 1.1681x over previous
#include <cuda_runtime.h>
#include <math.h>
#include <float.h>

#define BS 64
#define SEQ 128
#define IN_DIM 256
#define H 512
#define NSLOT 4096
#define MDIM 128
#define RHEADS 4
#define OUTD 64
#define GAMMA_F 0.95f
#define JH (4 * H)               /* 2048 */
#define QW (RHEADS * MDIM)       /* 512  */
#define OUTW (H + RHEADS * MDIM) /* 1024 */
#define KSPL 8
#define RVCH 16

/* ------------------- persistent device state -------------------------------- */
__device__ float g_mem[(size_t)BS * NSLOT * MDIM];
__device__ float g_rw[BS * RHEADS * NSLOT];
__device__ float g_uw[BS * NSLOT];
__device__ float g_h[BS * H];
__device__ float g_c[BS * H];
__device__ float g_zx[(size_t)SEQ * BS * JH];
__device__ float g_zpart[KSPL * BS * JH];
__device__ float g_qpart[KSPL * BS * QW];
__device__ float g_qall[(size_t)SEQ * BS * QW];
__device__ int   g_idx[BS * RHEADS];
__device__ float g_alpha_s[BS * RHEADS];
__device__ float g_logits[BS * RHEADS * NSLOT];
__device__ float g_lmax[BS * RVCH * RHEADS];
__device__ float g_wwsum[BS * NSLOT];
__device__ float g_hist_h[(size_t)SEQ * BS * H];
__device__ float g_rvpart[(size_t)SEQ * RVCH * BS * QW];
__device__ float g_normQb[BS];
__device__ float g_normM_part[BS * 16];

__device__ __forceinline__ float sigmoidf_(float v) { return 1.f / (1.f + expf(-v)); }

/* ------------------- init ---------------------------------------------------- */
__global__ void k_init(const float* __restrict__ alpha) {
    int i = blockIdx.x * 256 + threadIdx.x;
    if (i < BS * H) { g_h[i] = 0.f; g_c[i] = 0.f; }
    if (i < BS * RHEADS) g_alpha_s[i] = sigmoidf_(alpha[i]);
}

/* ------------------- zx precompute ------------------------------------------ */
__global__ void k_zx(const float* __restrict__ x, const float* __restrict__ y,
                     const float* __restrict__ Wl, const float* __restrict__ bl, int t0) {
    __shared__ float s_in[16][68];
    int tid = threadIdx.x;
    int tj = tid & 15, tb = tid >> 4;
    int j0 = blockIdx.x * 64;
    int t  = blockIdx.y + t0;
    float acc[4][4];
#pragma unroll
    for (int i = 0; i < 4; i++)
#pragma unroll
        for (int jj = 0; jj < 4; jj++) acc[i][jj] = 0.f;

    for (int k0 = 0; k0 < IN_DIM; k0 += 16) {
        for (int l = tid; l < 1024; l += 256) {
            int kk = l & 15, b = l >> 4;
            s_in[kk][b] = x[((size_t)b * SEQ + t) * IN_DIM + k0 + kk];
        }
        __syncthreads();
#pragma unroll 4
        for (int kk = 0; kk < 16; kk++) {
            float4 av = *reinterpret_cast<const float4*>(&s_in[kk][tb * 4]);
            float4 wv = *reinterpret_cast<const float4*>(&Wl[(size_t)(k0 + kk) * JH + j0 + tj * 4]);
            const float* a = (const float*)&av;
            const float* w = (const float*)&wv;
#pragma unroll
            for (int bi = 0; bi < 4; bi++)
#pragma unroll
                for (int ji = 0; ji < 4; ji++) acc[bi][ji] += a[bi] * w[ji];
        }
        __syncthreads();
    }
    float4 bv = *reinterpret_cast<const float4*>(&bl[j0 + tj * 4]);
    float4 wy = *reinterpret_cast<const float4*>(&Wl[(size_t)IN_DIM * JH + j0 + tj * 4]);
    const float* bb = (const float*)&bv;
    const float* wyp = (const float*)&wy;
#pragma unroll
    for (int bi = 0; bi < 4; bi++) {
        int b = tb * 4 + bi;
        float yb = (t > 0) ? y[b * SEQ + t - 1] : 0.f;
        float4 o;
        o.x = acc[bi][0] + bb[0] + yb * wyp[0];
        o.y = acc[bi][1] + bb[1] + yb * wyp[1];
        o.z = acc[bi][2] + bb[2] + yb * wyp[2];
        o.w = acc[bi][3] + bb[3] + yb * wyp[3];
        *reinterpret_cast<float4*>(&g_zx[((size_t)t * BS + b) * JH + j0 + tj * 4]) = o;
    }
}

/* ------------------- recurrent GEMM partial --------------------------------- */
__global__ void k_rec(const float* __restrict__ Wl) {
    __shared__ float s_in[16][68];
    int tid = threadIdx.x;
    int tj = tid & 15, tb = tid >> 4;
    int j0 = blockIdx.x * 64;
    int s  = blockIdx.y;
    int kbase = s * (H / KSPL);
    float acc[4][4];
#pragma unroll
    for (int i = 0; i < 4; i++)
#pragma unroll
        for (int jj = 0; jj < 4; jj++) acc[i][jj] = 0.f;

    for (int k0 = 0; k0 < H / KSPL; k0 += 16) {
        for (int l = tid; l < 1024; l += 256) {
            int kk = l & 15, b = l >> 4;
            s_in[kk][b] = g_h[b * H + kbase + k0 + kk];
        }
        __syncthreads();
#pragma unroll 4
        for (int kk = 0; kk < 16; kk++) {
            float4 av = *reinterpret_cast<const float4*>(&s_in[kk][tb * 4]);
            float4 wv = *reinterpret_cast<const float4*>(
                &Wl[(size_t)(IN_DIM + 1 + kbase + k0 + kk) * JH + j0 + tj * 4]);
            const float* a = (const float*)&av;
            const float* w = (const float*)&wv;
#pragma unroll
            for (int bi = 0; bi < 4; bi++)
#pragma unroll
                for (int ji = 0; ji < 4; ji++) acc[bi][ji] += a[bi] * w[ji];
        }
        __syncthreads();
    }
#pragma unroll
    for (int bi = 0; bi < 4; bi++) {
        int b = tb * 4 + bi;
        float4 o;
        o.x = acc[bi][0]; o.y = acc[bi][1]; o.z = acc[bi][2]; o.w = acc[bi][3];
        *reinterpret_cast<float4*>(&g_zpart[((size_t)s * BS + b) * JH + j0 + tj * 4]) = o;
    }
}

/* ------------------- gates --------------------------------------------------- */
__global__ void k_gates(int t) {
    int i = blockIdx.x * 256 + threadIdx.x;
    if (i >= BS * H) return;
    int b = i / H, hh = i % H;
    size_t zbase = ((size_t)t * BS + b) * JH;
    float zg[4];
#pragma unroll
    for (int g = 0; g < 4; g++) {
        float v = g_zx[zbase + g * H + hh];
#pragma unroll
        for (int s = 0; s < KSPL; s++)
            v += g_zpart[((size_t)s * BS + b) * JH + g * H + hh];
        zg[g] = v;
    }
    float f  = sigmoidf_(zg[0]);
    float ig = sigmoidf_(zg[1]);
    float o  = sigmoidf_(zg[2]);
    float u  = tanhf(zg[3]);
    float c  = f * g_c[i] + ig * u;
    float h  = o * tanhf(c);
    g_c[i] = c; g_h[i] = h;
    g_hist_h[((size_t)t * BS + b) * H + hh] = h;
}

/* ------------------- query GEMM partial -------------------------------------- */
__global__ void k_query(const float* __restrict__ Wm) {
    __shared__ float s_in[16][68];
    int tid = threadIdx.x;
    int tj = tid & 15, tb = tid >> 4;
    int j0 = blockIdx.x * 64;
    int s  = blockIdx.y;
    int kbase = s * (H / KSPL);
    float acc[4][4];
#pragma unroll
    for (int i = 0; i < 4; i++)
#pragma unroll
        for (int jj = 0; jj < 4; jj++) acc[i][jj] = 0.f;

    for (int k0 = 0; k0 < H / KSPL; k0 += 16) {
        for (int l = tid; l < 1024; l += 256) {
            int kk = l & 15, b = l >> 4;
            s_in[kk][b] = g_h[b * H + kbase + k0 + kk];
        }
        __syncthreads();
#pragma unroll 4
        for (int kk = 0; kk < 16; kk++) {
            float4 av = *reinterpret_cast<const float4*>(&s_in[kk][tb * 4]);
            float4 wv = *reinterpret_cast<const float4*>(
                &Wm[(size_t)(kbase + k0 + kk) * QW + j0 + tj * 4]);
            const float* a = (const float*)&av;
            const float* w = (const float*)&wv;
#pragma unroll
            for (int bi = 0; bi < 4; bi++)
#pragma unroll
                for (int ji = 0; ji < 4; ji++) acc[bi][ji] += a[bi] * w[ji];
        }
        __syncthreads();
    }
#pragma unroll
    for (int bi = 0; bi < 4; bi++) {
        int b = tb * 4 + bi;
        float4 o;
        o.x = acc[bi][0]; o.y = acc[bi][1]; o.z = acc[bi][2]; o.w = acc[bi][3];
        *reinterpret_cast<float4*>(&g_qpart[((size_t)s * BS + b) * QW + j0 + tj * 4]) = o;
    }
}

/* ------------------- combine q partials -------------------------------------- */
__global__ void k_qcomb(const float* __restrict__ bm, int t) {
    int l = blockIdx.x * 256 + threadIdx.x;
    if (l >= BS * QW) return;
    int b = l >> 9, j = l & 511;
    float v = bm[j];
#pragma unroll
    for (int s = 0; s < KSPL; s++) v += g_qpart[((size_t)s * BS + b) * QW + j];
    g_qall[((size_t)t * BS + b) * QW + j] = v;
}

/* ------------------- initial select ------------------------------------------ */
__global__ void k_select0() {
    int b = blockIdx.x;
    int tid = threadIdx.x;
    __shared__ float sv[256];
    __shared__ int   si[256];
    __shared__ int   picked[RHEADS];
    const float* uw = &g_uw[(size_t)b * NSLOT];
    for (int r = 0; r < RHEADS; r++) {
        float bestv = FLT_MAX;
        int besti = 0x7fffffff;
        for (int n = tid; n < NSLOT; n += 256) {
            bool skip = false;
            for (int p = 0; p < r; p++) if (picked[p] == n) skip = true;
            if (skip) continue;
            float v = uw[n];
            if (v < bestv || (v == bestv && n < besti)) { bestv = v; besti = n; }
        }
        sv[tid] = bestv; si[tid] = besti;
        __syncthreads();
        for (int s = 128; s > 0; s >>= 1) {
            if (tid < s) {
                if (sv[tid + s] < sv[tid] || (sv[tid + s] == sv[tid] && si[tid + s] < si[tid])) {
                    sv[tid] = sv[tid + s]; si[tid] = si[tid + s];
                }
            }
            __syncthreads();
        }
        if (tid == 0) { picked[r] = si[0]; g_idx[b * RHEADS + r] = si[0]; }
        __syncthreads();
    }
}

/* ------------------- memupd(t): update+logits+maxes+norms+readvec(t-1) ------- */
/* Round-5 proven body: NO launch_bounds, NO unroll pragma on the row loop       */
__global__ void k_memupd(int t) {
    int b  = blockIdx.y;
    int n0 = blockIdx.x * 256;
    __shared__ float sq[RHEADS][MDIM];
    __shared__ float srw[RHEADS][256];
    __shared__ float sal[RHEADS];
    __shared__ int   sidx[RHEADS];
    __shared__ float sredn[8];
    __shared__ float smax[8][RHEADS];
    __shared__ float s_red[256];
    __shared__ float sacc[8][QW];
    int tid = threadIdx.x;

    for (int l = tid; l < QW; l += 256)
        sq[l >> 7][l & 127] = g_qall[((size_t)t * BS + b) * QW + l];
    for (int l = tid; l < RHEADS * 256; l += 256) {
        int r = l >> 8, nn = l & 255;
        srw[r][nn] = g_rw[((size_t)b * RHEADS + r) * NSLOT + n0 + nn];
    }
    if (tid < RHEADS) { sal[tid] = g_alpha_s[b * RHEADS + tid]; sidx[tid] = g_idx[b * RHEADS + tid]; }
    __syncthreads();

    if (blockIdx.x == 0) {
        float local = 0.f;
        for (int l = tid; l < QW; l += 256) {
            float v = sq[l >> 7][l & 127];
            local += v * v;
        }
        s_red[tid] = local;
        __syncthreads();
        for (int s = 128; s > 0; s >>= 1) {
            if (tid < s) s_red[tid] += s_red[tid + s];
            __syncthreads();
        }
        if (tid == 0) g_normQb[b] = s_red[0];
        __syncthreads();
    }

    int warp = tid >> 5, lane = tid & 31;
    float normp = 0.f;
    float m0 = -FLT_MAX, m1 = -FLT_MAX, m2 = -FLT_MAX, m3 = -FLT_MAX;
    float rva[RHEADS][4];
#pragma unroll
    for (int r = 0; r < RHEADS; r++)
#pragma unroll
        for (int c = 0; c < 4; c++) rva[r][c] = 0.f;

    for (int row = warp; row < 256; row += 8) {
        int n = n0 + row;
        float r0w = srw[0][row], r1w = srw[1][row], r2w = srw[2][row], r3w = srw[3][row];
        float w0 = sal[0] * r0w; if (n == sidx[0]) w0 += 1.f - sal[0];
        float w1 = sal[1] * r1w; if (n == sidx[1]) w1 += 1.f - sal[1];
        float w2 = sal[2] * r2w; if (n == sidx[2]) w2 += 1.f - sal[2];
        float w3 = sal[3] * r3w; if (n == sidx[3]) w3 += 1.f - sal[3];
        float* mp = &g_mem[((size_t)b * NSLOT + n) * MDIM + lane * 4];
        float4 v = *reinterpret_cast<float4*>(mp);
        float* vv = (float*)&v;
        float d0 = 0.f, d1 = 0.f, d2 = 0.f, d3 = 0.f;
#pragma unroll
        for (int cpt = 0; cpt < 4; cpt++) {
            int m = lane * 4 + cpt;
            float pre = vv[cpt];
            rva[0][cpt] += r0w * pre; rva[1][cpt] += r1w * pre;
            rva[2][cpt] += r2w * pre; rva[3][cpt] += r3w * pre;
            float q0 = sq[0][m], q1 = sq[1][m], q2 = sq[2][m], q3 = sq[3][m];
            float nv = pre + w0 * q0 + w1 * q1 + w2 * q2 + w3 * q3;
            d0 += q0 * nv; d1 += q1 * nv; d2 += q2 * nv; d3 += q3 * nv;
            normp += nv * nv;
            vv[cpt] = nv;
        }
        *reinterpret_cast<float4*>(mp) = v;
#pragma unroll
        for (int off = 16; off > 0; off >>= 1) {
            d0 += __shfl_down_sync(0xffffffffu, d0, off);
            d1 += __shfl_down_sync(0xffffffffu, d1, off);
            d2 += __shfl_down_sync(0xffffffffu, d2, off);
            d3 += __shfl_down_sync(0xffffffffu, d3, off);
        }
        if (lane == 0) {
            g_logits[((size_t)b * RHEADS + 0) * NSLOT + n] = d0;
            g_logits[((size_t)b * RHEADS + 1) * NSLOT + n] = d1;
            g_logits[((size_t)b * RHEADS + 2) * NSLOT + n] = d2;
            g_logits[((size_t)b * RHEADS + 3) * NSLOT + n] = d3;
            g_wwsum[(size_t)b * NSLOT + n] = w0 + w1 + w2 + w3;
            m0 = fmaxf(m0, d0); m1 = fmaxf(m1, d1);
            m2 = fmaxf(m2, d2); m3 = fmaxf(m3, d3);
        }
    }
#pragma unroll
    for (int off = 16; off > 0; off >>= 1) normp += __shfl_down_sync(0xffffffffu, normp, off);
    if (lane == 0) {
        sredn[warp] = normp;
        smax[warp][0] = m0; smax[warp][1] = m1; smax[warp][2] = m2; smax[warp][3] = m3;
    }

#pragma unroll
    for (int r = 0; r < RHEADS; r++)
#pragma unroll
        for (int c = 0; c < 4; c++) sacc[warp][r * MDIM + lane * 4 + c] = rva[r][c];
    __syncthreads();

    if (tid == 0) {
        float s = 0.f;
        for (int i = 0; i < 8; i++) s += sredn[i];
        g_normM_part[b * 16 + blockIdx.x] = s;
    }
    if (tid < RHEADS) {
        float mm = smax[0][tid];
#pragma unroll
        for (int w = 1; w < 8; w++) mm = fmaxf(mm, smax[w][tid]);
        g_lmax[((size_t)b * RVCH + blockIdx.x) * RHEADS + tid] = mm;
    }
    if (t > 0) {
        for (int l = tid; l < QW; l += 256) {
            float s = 0.f;
#pragma unroll
            for (int w = 0; w < 8; w++) s += sacc[w][l];
            g_rvpart[(((size_t)(t - 1) * RVCH + blockIdx.x) * BS + b) * QW + l] = s;
        }
    }
}

/* ------------------- exp/normalize: one head per block ----------------------- */
/* grid (RHEADS, BS) = 256 blocks, 256 threads: spreads MUFU over the chip       */
__global__ void k_expw() {
    int g = blockIdx.x, b = blockIdx.y;
    int tid = threadIdx.x;
    __shared__ float red[256];
    __shared__ float s_invscale;

    float v = g_normM_part[tid] + g_normM_part[tid + 256] +
              g_normM_part[tid + 512] + g_normM_part[tid + 768];
    red[tid] = v;
    __syncthreads();
    for (int s = 128; s > 0; s >>= 1) {
        if (tid < s) red[tid] += red[tid + s];
        __syncthreads();
    }
    float nm = red[0];
    __syncthreads();
    red[tid] = (tid < BS) ? g_normQb[tid] : 0.f;
    __syncthreads();
    for (int s = 128; s > 0; s >>= 1) {
        if (tid < s) red[tid] += red[tid + s];
        __syncthreads();
    }
    if (tid == 0) s_invscale = 1.f / (sqrtf(red[0]) * sqrtf(nm));
    __syncthreads();
    float invs = s_invscale;

    const float* lg = &g_logits[((size_t)b * RHEADS + g) * NSLOT];
    float* rw = &g_rw[((size_t)b * RHEADS + g) * NSLOT];

    float mxr = -FLT_MAX;
#pragma unroll
    for (int ch = 0; ch < RVCH; ch++)
        mxr = fmaxf(mxr, g_lmax[((size_t)b * RVCH + ch) * RHEADS + g]);
    float mx = mxr * invs;

    float e[16];
    float sum = 0.f;
#pragma unroll
    for (int i = 0; i < 16; i++) {
        float t = expf(lg[tid + i * 256] * invs - mx);
        e[i] = t; sum += t;
    }
    red[tid] = sum;
    __syncthreads();
    for (int s = 128; s > 0; s >>= 1) {
        if (tid < s) red[tid] += red[tid + s];
        __syncthreads();
    }
    float inv = 1.f / red[0];
#pragma unroll
    for (int i = 0; i < 16; i++) rw[tid + i * 256] = e[i] * inv;
}

/* ------------------- uw update + single-pass top-4 select -------------------- */
/* grid BS, 512 threads                                                           */
__global__ void k_uwsel() {
    int b = blockIdx.x, tid = threadIdx.x;
    __shared__ float suw[NSLOT];
    __shared__ float s4v[512][4];
    __shared__ int   s4i[512][4];

    for (int n = tid; n < NSLOT; n += 512) {
        size_t base = (size_t)b * RHEADS * NSLOT;
        float rs = g_rw[base + n] + g_rw[base + NSLOT + n] +
                   g_rw[base + 2 * NSLOT + n] + g_rw[base + 3 * NSLOT + n];
        size_t ui = (size_t)b * NSLOT + n;
        float u = GAMMA_F * g_uw[ui] + rs + g_wwsum[ui];
        g_uw[ui] = u;
        suw[n] = u;
    }
    __syncthreads();

    float tv[4]; int ti[4];
#pragma unroll
    for (int k = 0; k < 4; k++) { tv[k] = FLT_MAX; ti[k] = 0x7fffffff; }
    for (int n = tid; n < NSLOT; n += 512) {
        float v = suw[n];
        if (v < tv[3] || (v == tv[3] && n < ti[3])) {
            int k = 3;
            while (k > 0 && (v < tv[k - 1] || (v == tv[k - 1] && n < ti[k - 1]))) {
                tv[k] = tv[k - 1]; ti[k] = ti[k - 1]; k--;
            }
            tv[k] = v; ti[k] = n;
        }
    }
#pragma unroll
    for (int k = 0; k < 4; k++) { s4v[tid][k] = tv[k]; s4i[tid][k] = ti[k]; }
    __syncthreads();

    for (int s = 256; s > 0; s >>= 1) {
        if (tid < s) {
            float av[4], bv[4], ov[4];
            int ai[4], bi[4], oi[4];
#pragma unroll
            for (int k = 0; k < 4; k++) {
                av[k] = s4v[tid][k];     ai[k] = s4i[tid][k];
                bv[k] = s4v[tid + s][k]; bi[k] = s4i[tid + s][k];
            }
            int a = 0, c = 0;
#pragma unroll
            for (int k = 0; k < 4; k++) {
                bool takeA = (av[a] < bv[c]) || (av[a] == bv[c] && ai[a] < bi[c]);
                if (takeA) { ov[k] = av[a]; oi[k] = ai[a]; a++; }
                else       { ov[k] = bv[c]; oi[k] = bi[c]; c++; }
            }
#pragma unroll
            for (int k = 0; k < 4; k++) { s4v[tid][k] = ov[k]; s4i[tid][k] = oi[k]; }
        }
        __syncthreads();
    }
    if (tid < RHEADS) g_idx[b * RHEADS + tid] = s4i[0][tid];
}

/* ------------------- final mem copy-out + readvec(SEQ-1) --------------------- */
__global__ void k_memcopy_rv(float* __restrict__ out_mem) {
    int b  = blockIdx.y;
    int n0 = blockIdx.x * 256;
    int tid = threadIdx.x;
    int warp = tid >> 5, lane = tid & 31;
    __shared__ float srw[RHEADS][256];
    __shared__ float sacc[8][QW];

    for (int l = tid; l < RHEADS * 256; l += 256) {
        int r = l >> 8, nn = l & 255;
        srw[r][nn] = g_rw[((size_t)b * RHEADS + r) * NSLOT + n0 + nn];
    }
    __syncthreads();

    float rva[RHEADS][4];
#pragma unroll
    for (int r = 0; r < RHEADS; r++)
#pragma unroll
        for (int c = 0; c < 4; c++) rva[r][c] = 0.f;

    for (int row = warp; row < 256; row += 8) {
        int n = n0 + row;
        size_t off = ((size_t)b * NSLOT + n) * MDIM + lane * 4;
        float4 v = *reinterpret_cast<const float4*>(&g_mem[off]);
        *reinterpret_cast<float4*>(&out_mem[off]) = v;
        const float* vv = (const float*)&v;
#pragma unroll
        for (int r = 0; r < RHEADS; r++) {
            float w = srw[r][row];
#pragma unroll
            for (int c = 0; c < 4; c++) rva[r][c] += w * vv[c];
        }
    }
#pragma unroll
    for (int r = 0; r < RHEADS; r++)
#pragma unroll
        for (int c = 0; c < 4; c++) sacc[warp][r * MDIM + lane * 4 + c] = rva[r][c];
    __syncthreads();
    for (int l = tid; l < QW; l += 256) {
        float s = 0.f;
#pragma unroll
        for (int w = 0; w < 8; w++) s += sacc[w][l];
        g_rvpart[(((size_t)(SEQ - 1) * RVCH + blockIdx.x) * BS + b) * QW + l] = s;
    }
}

/* ------------------- final projection + softmax ------------------------------ */
__global__ void k_final(const float* __restrict__ Wf, const float* __restrict__ bf,
                        float* __restrict__ out) {
    extern __shared__ float sm[];
    float (*svv)[OUTW] = (float (*)[OUTW])sm;
    float* red = sm + 16 * OUTW;
    int tid = threadIdx.x;
    int r0 = blockIdx.x * 16;
    int t  = r0 / BS;
    int b0 = r0 % BS;

    for (int l = tid; l < 16 * H; l += 128) {
        int rr = l >> 9, k = l & 511;
        svv[rr][k] = g_hist_h[((size_t)(r0 + rr)) * H + k];
    }
    for (int l = tid; l < 16 * QW; l += 128) {
        int rr = l >> 9, k = l & 511;
        float s = 0.f;
#pragma unroll
        for (int c = 0; c < RVCH; c++)
            s += g_rvpart[(((size_t)t * RVCH + c) * BS + (b0 + rr)) * QW + k];
        svv[rr][H + k] = s;
    }
    __syncthreads();

    int half = tid >> 6, col = tid & 63;
    float accs[8];
#pragma unroll
    for (int rr = 0; rr < 8; rr++) accs[rr] = bf[col];
    for (int k = 0; k < OUTW; k++) {
        float w = Wf[(size_t)k * OUTD + col];
#pragma unroll
        for (int rr = 0; rr < 8; rr++) accs[rr] += svv[half * 8 + rr][k] * w;
    }
    for (int rr = 0; rr < 8; rr++) {
        red[tid] = accs[rr];
        __syncthreads();
        for (int s = 32; s > 0; s >>= 1) {
            if ((tid & 63) < s) red[tid] = fmaxf(red[tid], red[tid + s]);
            __syncthreads();
        }
        float mx = red[half * 64];
        __syncthreads();
        float e = expf(accs[rr] - mx);
        red[tid] = e;
        __syncthreads();
        for (int s = 32; s > 0; s >>= 1) {
            if ((tid & 63) < s) red[tid] += red[tid + s];
            __syncthreads();
        }
        float denom = red[half * 64];
        __syncthreads();
        int b = b0 + half * 8 + rr;
        out[((size_t)b * SEQ + t) * OUTD + col] = e / denom;
    }
}

/* ------------------- host: two-stream fork/join pipeline --------------------- */
extern "C" void kernel_launch(void* const* d_in, const int* in_sizes, int n_in,
                              void* d_out, int out_size) {
    const float* x            = (const float*)d_in[0];
    const float* y            = (const float*)d_in[1];
    const float* memory       = (const float*)d_in[2];
    const float* read_weight  = (const float*)d_in[3];
    const float* usage_weight = (const float*)d_in[4];
    const float* Wl           = (const float*)d_in[5];
    const float* bl           = (const float*)d_in[6];
    const float* Wm           = (const float*)d_in[7];
    const float* bm           = (const float*)d_in[8];
    const float* Wf           = (const float*)d_in[9];
    const float* bf           = (const float*)d_in[10];
    const float* alpha        = (const float*)d_in[11];
    float* out = (float*)d_out;

    static cudaStream_t s1;
    static cudaEvent_t evFork, evJoin, evQ[SEQ];
    static int inited = 0;
    if (!inited) {
        cudaStreamCreateWithFlags(&s1, cudaStreamNonBlocking);
        cudaEventCreateWithFlags(&evFork, cudaEventDisableTiming);
        cudaEventCreateWithFlags(&evJoin, cudaEventDisableTiming);
        for (int t = 0; t < SEQ; t++)
            cudaEventCreateWithFlags(&evQ[t], cudaEventDisableTiming);
        cudaFuncSetAttribute(k_final, cudaFuncAttributeMaxDynamicSharedMemorySize,
                             (16 * OUTW + 128) * (int)sizeof(float));
        inited = 1;
    }

    cudaMemcpyToSymbolAsync(g_mem, memory, sizeof(float) * (size_t)BS * NSLOT * MDIM, 0,
                            cudaMemcpyDeviceToDevice, 0);
    cudaMemcpyToSymbolAsync(g_rw, read_weight, sizeof(float) * BS * RHEADS * NSLOT, 0,
                            cudaMemcpyDeviceToDevice, 0);
    cudaMemcpyToSymbolAsync(g_uw, usage_weight, sizeof(float) * BS * NSLOT, 0,
                            cudaMemcpyDeviceToDevice, 0);
    k_init<<<(BS * H + 255) / 256, 256>>>(alpha);
    k_select0<<<BS, 256>>>();

    cudaEventRecord(evFork, 0);
    cudaStreamWaitEvent(s1, evFork, 0);

    /* controller chain on s1 */
    k_zx<<<dim3(32, 1), 256, 0, s1>>>(x, y, Wl, bl, 0);
    k_rec<<<dim3(32, KSPL), 256, 0, s1>>>(Wl);
    k_gates<<<(BS * H) / 256, 256, 0, s1>>>(0);
    k_query<<<dim3(8, KSPL), 256, 0, s1>>>(Wm);
    k_qcomb<<<(BS * QW + 255) / 256, 256, 0, s1>>>(bm, 0);
    cudaEventRecord(evQ[0], s1);
    k_zx<<<dim3(32, SEQ - 1), 256, 0, s1>>>(x, y, Wl, bl, 1);
    for (int t = 1; t < SEQ; t++) {
        k_rec<<<dim3(32, KSPL), 256, 0, s1>>>(Wl);
        k_gates<<<(BS * H) / 256, 256, 0, s1>>>(t);
        k_query<<<dim3(8, KSPL), 256, 0, s1>>>(Wm);
        k_qcomb<<<(BS * QW + 255) / 256, 256, 0, s1>>>(bm, t);
        cudaEventRecord(evQ[t], s1);
    }
    cudaEventRecord(evJoin, s1);

    /* memory chain on capture stream */
    for (int t = 0; t < SEQ; t++) {
        cudaStreamWaitEvent(0, evQ[t], 0);
        k_memupd<<<dim3(16, BS), 256>>>(t);
        k_expw<<<dim3(RHEADS, BS), 256>>>();
        k_uwsel<<<BS, 512>>>();
    }
    cudaStreamWaitEvent(0, evJoin, 0);

    size_t np = (size_t)BS * SEQ * OUTD;
    size_t nm = (size_t)BS * NSLOT * MDIM;
    size_t nr = (size_t)BS * RHEADS * NSLOT;
    k_memcopy_rv<<<dim3(16, BS), 256>>>(out + np);
    cudaMemcpyFromSymbolAsync(out + np + nm, g_rw, nr * sizeof(float), 0,
                              cudaMemcpyDeviceToDevice, 0);
    cudaMemcpyFromSymbolAsync(out + np + nm + nr, g_uw, (size_t)BS * NSLOT * sizeof(float), 0,
                              cudaMemcpyDeviceToDevice, 0);
    k_final<<<SEQ * BS / 16, 128, (16 * OUTW + 128) * sizeof(float)>>>(Wf, bf, out);
}

// round 8
// speedup vs baseline: 1.2971x; 1.1105x over previous
#include <cuda_runtime.h>
#include <math.h>
#include <float.h>

#define BS 64
#define SEQ 128
#define IN_DIM 256
#define H 512
#define NSLOT 4096
#define MDIM 128
#define RHEADS 4
#define OUTD 64
#define GAMMA_F 0.95f
#define JH (4 * H)               /* 2048 */
#define QW (RHEADS * MDIM)       /* 512  */
#define OUTW (H + RHEADS * MDIM) /* 1024 */
#define KSPL 8
#define RVCH 16

/* ------------------- persistent device state -------------------------------- */
__device__ float g_mem[(size_t)BS * NSLOT * MDIM];
__device__ float g_rw[BS * RHEADS * NSLOT];
__device__ float g_uw[BS * NSLOT];
__device__ float g_h[BS * H];
__device__ float g_c[BS * H];
__device__ float g_zx[(size_t)SEQ * BS * JH];
__device__ float g_zpart[KSPL * BS * JH];
__device__ float g_qpart[KSPL * BS * QW];
__device__ float g_qall[(size_t)SEQ * BS * QW];
__device__ int   g_idx[BS * RHEADS];
__device__ float g_alpha_s[BS * RHEADS];
__device__ float g_logits[BS * RHEADS * NSLOT];
__device__ float g_lmax[BS * RVCH * RHEADS];
__device__ float g_wwsum[BS * NSLOT];
__device__ float g_hist_h[(size_t)SEQ * BS * H];
__device__ float g_rvpart[(size_t)SEQ * RVCH * BS * QW];
__device__ float g_normQb[BS];
__device__ float g_normM_part[BS * 16];

__device__ __forceinline__ float sigmoidf_(float v) { return 1.f / (1.f + expf(-v)); }

/* ------------------- init ---------------------------------------------------- */
__global__ void k_init(const float* __restrict__ alpha) {
    int i = blockIdx.x * 256 + threadIdx.x;
    if (i < BS * H) { g_h[i] = 0.f; g_c[i] = 0.f; }
    if (i < BS * RHEADS) g_alpha_s[i] = sigmoidf_(alpha[i]);
}

/* ------------------- zx precompute ------------------------------------------ */
__global__ void k_zx(const float* __restrict__ x, const float* __restrict__ y,
                     const float* __restrict__ Wl, const float* __restrict__ bl, int t0) {
    __shared__ float s_in[16][68];
    int tid = threadIdx.x;
    int tj = tid & 15, tb = tid >> 4;
    int j0 = blockIdx.x * 64;
    int t  = blockIdx.y + t0;
    float acc[4][4];
#pragma unroll
    for (int i = 0; i < 4; i++)
#pragma unroll
        for (int jj = 0; jj < 4; jj++) acc[i][jj] = 0.f;

    for (int k0 = 0; k0 < IN_DIM; k0 += 16) {
        for (int l = tid; l < 1024; l += 256) {
            int kk = l & 15, b = l >> 4;
            s_in[kk][b] = x[((size_t)b * SEQ + t) * IN_DIM + k0 + kk];
        }
        __syncthreads();
#pragma unroll 4
        for (int kk = 0; kk < 16; kk++) {
            float4 av = *reinterpret_cast<const float4*>(&s_in[kk][tb * 4]);
            float4 wv = *reinterpret_cast<const float4*>(&Wl[(size_t)(k0 + kk) * JH + j0 + tj * 4]);
            const float* a = (const float*)&av;
            const float* w = (const float*)&wv;
#pragma unroll
            for (int bi = 0; bi < 4; bi++)
#pragma unroll
                for (int ji = 0; ji < 4; ji++) acc[bi][ji] += a[bi] * w[ji];
        }
        __syncthreads();
    }
    float4 bv = *reinterpret_cast<const float4*>(&bl[j0 + tj * 4]);
    float4 wy = *reinterpret_cast<const float4*>(&Wl[(size_t)IN_DIM * JH + j0 + tj * 4]);
    const float* bb = (const float*)&bv;
    const float* wyp = (const float*)&wy;
#pragma unroll
    for (int bi = 0; bi < 4; bi++) {
        int b = tb * 4 + bi;
        float yb = (t > 0) ? y[b * SEQ + t - 1] : 0.f;
        float4 o;
        o.x = acc[bi][0] + bb[0] + yb * wyp[0];
        o.y = acc[bi][1] + bb[1] + yb * wyp[1];
        o.z = acc[bi][2] + bb[2] + yb * wyp[2];
        o.w = acc[bi][3] + bb[3] + yb * wyp[3];
        *reinterpret_cast<float4*>(&g_zx[((size_t)t * BS + b) * JH + j0 + tj * 4]) = o;
    }
}

/* ------------------- recurrent GEMM partial --------------------------------- */
__global__ void k_rec(const float* __restrict__ Wl) {
    __shared__ float s_in[16][68];
    int tid = threadIdx.x;
    int tj = tid & 15, tb = tid >> 4;
    int j0 = blockIdx.x * 64;
    int s  = blockIdx.y;
    int kbase = s * (H / KSPL);
    float acc[4][4];
#pragma unroll
    for (int i = 0; i < 4; i++)
#pragma unroll
        for (int jj = 0; jj < 4; jj++) acc[i][jj] = 0.f;

    for (int k0 = 0; k0 < H / KSPL; k0 += 16) {
        for (int l = tid; l < 1024; l += 256) {
            int kk = l & 15, b = l >> 4;
            s_in[kk][b] = g_h[b * H + kbase + k0 + kk];
        }
        __syncthreads();
#pragma unroll 4
        for (int kk = 0; kk < 16; kk++) {
            float4 av = *reinterpret_cast<const float4*>(&s_in[kk][tb * 4]);
            float4 wv = *reinterpret_cast<const float4*>(
                &Wl[(size_t)(IN_DIM + 1 + kbase + k0 + kk) * JH + j0 + tj * 4]);
            const float* a = (const float*)&av;
            const float* w = (const float*)&wv;
#pragma unroll
            for (int bi = 0; bi < 4; bi++)
#pragma unroll
                for (int ji = 0; ji < 4; ji++) acc[bi][ji] += a[bi] * w[ji];
        }
        __syncthreads();
    }
#pragma unroll
    for (int bi = 0; bi < 4; bi++) {
        int b = tb * 4 + bi;
        float4 o;
        o.x = acc[bi][0]; o.y = acc[bi][1]; o.z = acc[bi][2]; o.w = acc[bi][3];
        *reinterpret_cast<float4*>(&g_zpart[((size_t)s * BS + b) * JH + j0 + tj * 4]) = o;
    }
}

/* ------------------- gates --------------------------------------------------- */
__global__ void k_gates(int t) {
    int i = blockIdx.x * 256 + threadIdx.x;
    if (i >= BS * H) return;
    int b = i / H, hh = i % H;
    size_t zbase = ((size_t)t * BS + b) * JH;
    float zg[4];
#pragma unroll
    for (int g = 0; g < 4; g++) {
        float v = g_zx[zbase + g * H + hh];
#pragma unroll
        for (int s = 0; s < KSPL; s++)
            v += g_zpart[((size_t)s * BS + b) * JH + g * H + hh];
        zg[g] = v;
    }
    float f  = sigmoidf_(zg[0]);
    float ig = sigmoidf_(zg[1]);
    float o  = sigmoidf_(zg[2]);
    float u  = tanhf(zg[3]);
    float c  = f * g_c[i] + ig * u;
    float h  = o * tanhf(c);
    g_c[i] = c; g_h[i] = h;
    g_hist_h[((size_t)t * BS + b) * H + hh] = h;
}

/* ------------------- query GEMM partial -------------------------------------- */
__global__ void k_query(const float* __restrict__ Wm) {
    __shared__ float s_in[16][68];
    int tid = threadIdx.x;
    int tj = tid & 15, tb = tid >> 4;
    int j0 = blockIdx.x * 64;
    int s  = blockIdx.y;
    int kbase = s * (H / KSPL);
    float acc[4][4];
#pragma unroll
    for (int i = 0; i < 4; i++)
#pragma unroll
        for (int jj = 0; jj < 4; jj++) acc[i][jj] = 0.f;

    for (int k0 = 0; k0 < H / KSPL; k0 += 16) {
        for (int l = tid; l < 1024; l += 256) {
            int kk = l & 15, b = l >> 4;
            s_in[kk][b] = g_h[b * H + kbase + k0 + kk];
        }
        __syncthreads();
#pragma unroll 4
        for (int kk = 0; kk < 16; kk++) {
            float4 av = *reinterpret_cast<const float4*>(&s_in[kk][tb * 4]);
            float4 wv = *reinterpret_cast<const float4*>(
                &Wm[(size_t)(kbase + k0 + kk) * QW + j0 + tj * 4]);
            const float* a = (const float*)&av;
            const float* w = (const float*)&wv;
#pragma unroll
            for (int bi = 0; bi < 4; bi++)
#pragma unroll
                for (int ji = 0; ji < 4; ji++) acc[bi][ji] += a[bi] * w[ji];
        }
        __syncthreads();
    }
#pragma unroll
    for (int bi = 0; bi < 4; bi++) {
        int b = tb * 4 + bi;
        float4 o;
        o.x = acc[bi][0]; o.y = acc[bi][1]; o.z = acc[bi][2]; o.w = acc[bi][3];
        *reinterpret_cast<float4*>(&g_qpart[((size_t)s * BS + b) * QW + j0 + tj * 4]) = o;
    }
}

/* ------------------- combine q partials -------------------------------------- */
__global__ void k_qcomb(const float* __restrict__ bm, int t) {
    int l = blockIdx.x * 256 + threadIdx.x;
    if (l >= BS * QW) return;
    int b = l >> 9, j = l & 511;
    float v = bm[j];
#pragma unroll
    for (int s = 0; s < KSPL; s++) v += g_qpart[((size_t)s * BS + b) * QW + j];
    g_qall[((size_t)t * BS + b) * QW + j] = v;
}

/* ------------------- initial select ------------------------------------------ */
__global__ void k_select0() {
    int b = blockIdx.x;
    int tid = threadIdx.x;
    __shared__ float sv[256];
    __shared__ int   si[256];
    __shared__ int   picked[RHEADS];
    const float* uw = &g_uw[(size_t)b * NSLOT];
    for (int r = 0; r < RHEADS; r++) {
        float bestv = FLT_MAX;
        int besti = 0x7fffffff;
        for (int n = tid; n < NSLOT; n += 256) {
            bool skip = false;
            for (int p = 0; p < r; p++) if (picked[p] == n) skip = true;
            if (skip) continue;
            float v = uw[n];
            if (v < bestv || (v == bestv && n < besti)) { bestv = v; besti = n; }
        }
        sv[tid] = bestv; si[tid] = besti;
        __syncthreads();
        for (int s = 128; s > 0; s >>= 1) {
            if (tid < s) {
                if (sv[tid + s] < sv[tid] || (sv[tid + s] == sv[tid] && si[tid + s] < si[tid])) {
                    sv[tid] = sv[tid + s]; si[tid] = si[tid + s];
                }
            }
            __syncthreads();
        }
        if (tid == 0) { picked[r] = si[0]; g_idx[b * RHEADS + r] = si[0]; }
        __syncthreads();
    }
}

/* ------------------- memupd(t): update+logits+maxes+norms+readvec(t-1) ------- */
/* Round-5 proven body, byte-identical                                            */
__global__ void k_memupd(int t) {
    int b  = blockIdx.y;
    int n0 = blockIdx.x * 256;
    __shared__ float sq[RHEADS][MDIM];
    __shared__ float srw[RHEADS][256];
    __shared__ float sal[RHEADS];
    __shared__ int   sidx[RHEADS];
    __shared__ float sredn[8];
    __shared__ float smax[8][RHEADS];
    __shared__ float s_red[256];
    __shared__ float sacc[8][QW];
    int tid = threadIdx.x;

    for (int l = tid; l < QW; l += 256)
        sq[l >> 7][l & 127] = g_qall[((size_t)t * BS + b) * QW + l];
    for (int l = tid; l < RHEADS * 256; l += 256) {
        int r = l >> 8, nn = l & 255;
        srw[r][nn] = g_rw[((size_t)b * RHEADS + r) * NSLOT + n0 + nn];
    }
    if (tid < RHEADS) { sal[tid] = g_alpha_s[b * RHEADS + tid]; sidx[tid] = g_idx[b * RHEADS + tid]; }
    __syncthreads();

    if (blockIdx.x == 0) {
        float local = 0.f;
        for (int l = tid; l < QW; l += 256) {
            float v = sq[l >> 7][l & 127];
            local += v * v;
        }
        s_red[tid] = local;
        __syncthreads();
        for (int s = 128; s > 0; s >>= 1) {
            if (tid < s) s_red[tid] += s_red[tid + s];
            __syncthreads();
        }
        if (tid == 0) g_normQb[b] = s_red[0];
        __syncthreads();
    }

    int warp = tid >> 5, lane = tid & 31;
    float normp = 0.f;
    float m0 = -FLT_MAX, m1 = -FLT_MAX, m2 = -FLT_MAX, m3 = -FLT_MAX;
    float rva[RHEADS][4];
#pragma unroll
    for (int r = 0; r < RHEADS; r++)
#pragma unroll
        for (int c = 0; c < 4; c++) rva[r][c] = 0.f;

    for (int row = warp; row < 256; row += 8) {
        int n = n0 + row;
        float r0w = srw[0][row], r1w = srw[1][row], r2w = srw[2][row], r3w = srw[3][row];
        float w0 = sal[0] * r0w; if (n == sidx[0]) w0 += 1.f - sal[0];
        float w1 = sal[1] * r1w; if (n == sidx[1]) w1 += 1.f - sal[1];
        float w2 = sal[2] * r2w; if (n == sidx[2]) w2 += 1.f - sal[2];
        float w3 = sal[3] * r3w; if (n == sidx[3]) w3 += 1.f - sal[3];
        float* mp = &g_mem[((size_t)b * NSLOT + n) * MDIM + lane * 4];
        float4 v = *reinterpret_cast<float4*>(mp);
        float* vv = (float*)&v;
        float d0 = 0.f, d1 = 0.f, d2 = 0.f, d3 = 0.f;
#pragma unroll
        for (int cpt = 0; cpt < 4; cpt++) {
            int m = lane * 4 + cpt;
            float pre = vv[cpt];
            rva[0][cpt] += r0w * pre; rva[1][cpt] += r1w * pre;
            rva[2][cpt] += r2w * pre; rva[3][cpt] += r3w * pre;
            float q0 = sq[0][m], q1 = sq[1][m], q2 = sq[2][m], q3 = sq[3][m];
            float nv = pre + w0 * q0 + w1 * q1 + w2 * q2 + w3 * q3;
            d0 += q0 * nv; d1 += q1 * nv; d2 += q2 * nv; d3 += q3 * nv;
            normp += nv * nv;
            vv[cpt] = nv;
        }
        *reinterpret_cast<float4*>(mp) = v;
#pragma unroll
        for (int off = 16; off > 0; off >>= 1) {
            d0 += __shfl_down_sync(0xffffffffu, d0, off);
            d1 += __shfl_down_sync(0xffffffffu, d1, off);
            d2 += __shfl_down_sync(0xffffffffu, d2, off);
            d3 += __shfl_down_sync(0xffffffffu, d3, off);
        }
        if (lane == 0) {
            g_logits[((size_t)b * RHEADS + 0) * NSLOT + n] = d0;
            g_logits[((size_t)b * RHEADS + 1) * NSLOT + n] = d1;
            g_logits[((size_t)b * RHEADS + 2) * NSLOT + n] = d2;
            g_logits[((size_t)b * RHEADS + 3) * NSLOT + n] = d3;
            g_wwsum[(size_t)b * NSLOT + n] = w0 + w1 + w2 + w3;
            m0 = fmaxf(m0, d0); m1 = fmaxf(m1, d1);
            m2 = fmaxf(m2, d2); m3 = fmaxf(m3, d3);
        }
    }
#pragma unroll
    for (int off = 16; off > 0; off >>= 1) normp += __shfl_down_sync(0xffffffffu, normp, off);
    if (lane == 0) {
        sredn[warp] = normp;
        smax[warp][0] = m0; smax[warp][1] = m1; smax[warp][2] = m2; smax[warp][3] = m3;
    }

#pragma unroll
    for (int r = 0; r < RHEADS; r++)
#pragma unroll
        for (int c = 0; c < 4; c++) sacc[warp][r * MDIM + lane * 4 + c] = rva[r][c];
    __syncthreads();

    if (tid == 0) {
        float s = 0.f;
        for (int i = 0; i < 8; i++) s += sredn[i];
        g_normM_part[b * 16 + blockIdx.x] = s;
    }
    if (tid < RHEADS) {
        float mm = smax[0][tid];
#pragma unroll
        for (int w = 1; w < 8; w++) mm = fmaxf(mm, smax[w][tid]);
        g_lmax[((size_t)b * RVCH + blockIdx.x) * RHEADS + tid] = mm;
    }
    if (t > 0) {
        for (int l = tid; l < QW; l += 256) {
            float s = 0.f;
#pragma unroll
            for (int w = 0; w < 8; w++) s += sacc[w][l];
            g_rvpart[(((size_t)(t - 1) * RVCH + blockIdx.x) * BS + b) * QW + l] = s;
        }
    }
}

/* ------------------- fused softmax + uw + select, float4 everywhere ---------- */
/* grid BS, 512 threads                                                           */
__global__ void k_softmax_uw_sel() {
    int b = blockIdx.x, tid = threadIdx.x;
    __shared__ float red[512];
    __shared__ float suw[NSLOT];
    __shared__ float s4v[512][4];
    __shared__ int   s4i[512][4];
    __shared__ float s_invscale;

    /* global norms */
    float lm = g_normM_part[tid] + g_normM_part[tid + 512];
    red[tid] = lm;
    __syncthreads();
    for (int s = 256; s > 0; s >>= 1) {
        if (tid < s) red[tid] += red[tid + s];
        __syncthreads();
    }
    float nm = red[0];
    __syncthreads();
    red[tid] = (tid < BS) ? g_normQb[tid] : 0.f;
    __syncthreads();
    for (int s = 256; s > 0; s >>= 1) {
        if (tid < s) red[tid] += red[tid + s];
        __syncthreads();
    }
    if (tid == 0) s_invscale = 1.f / (sqrtf(red[0]) * sqrtf(nm));
    __syncthreads();
    float invs = s_invscale;

    /* 4 groups of 128 threads, one head each; float4 loads (8 per thread) */
    int g = tid >> 7, lt = tid & 127;
    const float4* lg4 = reinterpret_cast<const float4*>(
        &g_logits[((size_t)b * RHEADS + g) * NSLOT]);
    float4* rw4 = reinterpret_cast<float4*>(&g_rw[((size_t)b * RHEADS + g) * NSLOT]);

    float mxr = -FLT_MAX;
#pragma unroll
    for (int ch = 0; ch < RVCH; ch++)
        mxr = fmaxf(mxr, g_lmax[((size_t)b * RVCH + ch) * RHEADS + g]);
    float mx = mxr * invs;

    float4 e[8];
    float sum = 0.f;
#pragma unroll
    for (int i = 0; i < 8; i++) {
        float4 v = lg4[lt + i * 128];
        e[i].x = expf(v.x * invs - mx);
        e[i].y = expf(v.y * invs - mx);
        e[i].z = expf(v.z * invs - mx);
        e[i].w = expf(v.w * invs - mx);
        sum += e[i].x + e[i].y + e[i].z + e[i].w;
    }
    red[tid] = sum;
    __syncthreads();
    for (int s = 64; s > 0; s >>= 1) {
        if (lt < s) red[tid] += red[tid + s];
        __syncthreads();
    }
    float inv = 1.f / red[g << 7];
    __syncthreads();
#pragma unroll
    for (int i = 0; i < 8; i++) {
        float4 o;
        o.x = e[i].x * inv; o.y = e[i].y * inv;
        o.z = e[i].z * inv; o.w = e[i].w * inv;
        rw4[lt + i * 128] = o;
    }
    __syncthreads();

    /* uw update, float4 (1024 float4 over 512 threads = 2 iters) */
    {
        size_t base = (size_t)b * RHEADS * NSLOT;
        const float4* rwB = reinterpret_cast<const float4*>(&g_rw[base]);
        const float4* wwB = reinterpret_cast<const float4*>(&g_wwsum[(size_t)b * NSLOT]);
        float4* uwB = reinterpret_cast<float4*>(&g_uw[(size_t)b * NSLOT]);
        float4* suw4 = reinterpret_cast<float4*>(suw);
        const int NQ = NSLOT / 4;
#pragma unroll
        for (int it = 0; it < 2; it++) {
            int n4 = tid + it * 512;
            float4 r0 = rwB[n4];
            float4 r1 = rwB[NQ + n4];
            float4 r2 = rwB[2 * NQ + n4];
            float4 r3 = rwB[3 * NQ + n4];
            float4 ww = wwB[n4];
            float4 uo = uwB[n4];
            float4 u;
            u.x = GAMMA_F * uo.x + (r0.x + r1.x + r2.x + r3.x) + ww.x;
            u.y = GAMMA_F * uo.y + (r0.y + r1.y + r2.y + r3.y) + ww.y;
            u.z = GAMMA_F * uo.z + (r0.z + r1.z + r2.z + r3.z) + ww.z;
            u.w = GAMMA_F * uo.w + (r0.w + r1.w + r2.w + r3.w) + ww.w;
            uwB[n4] = u;
            suw4[n4] = u;
        }
    }
    __syncthreads();

    /* single-pass top-4: per-thread sorted top-4, then tree merge */
    float tv[4]; int ti[4];
#pragma unroll
    for (int k = 0; k < 4; k++) { tv[k] = FLT_MAX; ti[k] = 0x7fffffff; }
    for (int n = tid; n < NSLOT; n += 512) {
        float v = suw[n];
        if (v < tv[3] || (v == tv[3] && n < ti[3])) {
            int k = 3;
            while (k > 0 && (v < tv[k - 1] || (v == tv[k - 1] && n < ti[k - 1]))) {
                tv[k] = tv[k - 1]; ti[k] = ti[k - 1]; k--;
            }
            tv[k] = v; ti[k] = n;
        }
    }
#pragma unroll
    for (int k = 0; k < 4; k++) { s4v[tid][k] = tv[k]; s4i[tid][k] = ti[k]; }
    __syncthreads();

    for (int s = 256; s > 0; s >>= 1) {
        if (tid < s) {
            float av[4], bv[4], ov[4];
            int ai[4], bi[4], oi[4];
#pragma unroll
            for (int k = 0; k < 4; k++) {
                av[k] = s4v[tid][k];     ai[k] = s4i[tid][k];
                bv[k] = s4v[tid + s][k]; bi[k] = s4i[tid + s][k];
            }
            int a = 0, c = 0;
#pragma unroll
            for (int k = 0; k < 4; k++) {
                bool takeA = (av[a] < bv[c]) || (av[a] == bv[c] && ai[a] < bi[c]);
                if (takeA) { ov[k] = av[a]; oi[k] = ai[a]; a++; }
                else       { ov[k] = bv[c]; oi[k] = bi[c]; c++; }
            }
#pragma unroll
            for (int k = 0; k < 4; k++) { s4v[tid][k] = ov[k]; s4i[tid][k] = oi[k]; }
        }
        __syncthreads();
    }
    if (tid < RHEADS) g_idx[b * RHEADS + tid] = s4i[0][tid];
}

/* ------------------- final mem copy-out + readvec(SEQ-1) --------------------- */
__global__ void k_memcopy_rv(float* __restrict__ out_mem) {
    int b  = blockIdx.y;
    int n0 = blockIdx.x * 256;
    int tid = threadIdx.x;
    int warp = tid >> 5, lane = tid & 31;
    __shared__ float srw[RHEADS][256];
    __shared__ float sacc[8][QW];

    for (int l = tid; l < RHEADS * 256; l += 256) {
        int r = l >> 8, nn = l & 255;
        srw[r][nn] = g_rw[((size_t)b * RHEADS + r) * NSLOT + n0 + nn];
    }
    __syncthreads();

    float rva[RHEADS][4];
#pragma unroll
    for (int r = 0; r < RHEADS; r++)
#pragma unroll
        for (int c = 0; c < 4; c++) rva[r][c] = 0.f;

    for (int row = warp; row < 256; row += 8) {
        int n = n0 + row;
        size_t off = ((size_t)b * NSLOT + n) * MDIM + lane * 4;
        float4 v = *reinterpret_cast<const float4*>(&g_mem[off]);
        *reinterpret_cast<float4*>(&out_mem[off]) = v;
        const float* vv = (const float*)&v;
#pragma unroll
        for (int r = 0; r < RHEADS; r++) {
            float w = srw[r][row];
#pragma unroll
            for (int c = 0; c < 4; c++) rva[r][c] += w * vv[c];
        }
    }
#pragma unroll
    for (int r = 0; r < RHEADS; r++)
#pragma unroll
        for (int c = 0; c < 4; c++) sacc[warp][r * MDIM + lane * 4 + c] = rva[r][c];
    __syncthreads();
    for (int l = tid; l < QW; l += 256) {
        float s = 0.f;
#pragma unroll
        for (int w = 0; w < 8; w++) s += sacc[w][l];
        g_rvpart[(((size_t)(SEQ - 1) * RVCH + blockIdx.x) * BS + b) * QW + l] = s;
    }
}

/* ------------------- final projection + softmax ------------------------------ */
__global__ void k_final(const float* __restrict__ Wf, const float* __restrict__ bf,
                        float* __restrict__ out) {
    extern __shared__ float sm[];
    float (*svv)[OUTW] = (float (*)[OUTW])sm;
    float* red = sm + 16 * OUTW;
    int tid = threadIdx.x;
    int r0 = blockIdx.x * 16;
    int t  = r0 / BS;
    int b0 = r0 % BS;

    for (int l = tid; l < 16 * H; l += 128) {
        int rr = l >> 9, k = l & 511;
        svv[rr][k] = g_hist_h[((size_t)(r0 + rr)) * H + k];
    }
    for (int l = tid; l < 16 * QW; l += 128) {
        int rr = l >> 9, k = l & 511;
        float s = 0.f;
#pragma unroll
        for (int c = 0; c < RVCH; c++)
            s += g_rvpart[(((size_t)t * RVCH + c) * BS + (b0 + rr)) * QW + k];
        svv[rr][H + k] = s;
    }
    __syncthreads();

    int half = tid >> 6, col = tid & 63;
    float accs[8];
#pragma unroll
    for (int rr = 0; rr < 8; rr++) accs[rr] = bf[col];
    for (int k = 0; k < OUTW; k++) {
        float w = Wf[(size_t)k * OUTD + col];
#pragma unroll
        for (int rr = 0; rr < 8; rr++) accs[rr] += svv[half * 8 + rr][k] * w;
    }
    for (int rr = 0; rr < 8; rr++) {
        red[tid] = accs[rr];
        __syncthreads();
        for (int s = 32; s > 0; s >>= 1) {
            if ((tid & 63) < s) red[tid] = fmaxf(red[tid], red[tid + s]);
            __syncthreads();
        }
        float mx = red[half * 64];
        __syncthreads();
        float e = expf(accs[rr] - mx);
        red[tid] = e;
        __syncthreads();
        for (int s = 32; s > 0; s >>= 1) {
            if ((tid & 63) < s) red[tid] += red[tid + s];
            __syncthreads();
        }
        float denom = red[half * 64];
        __syncthreads();
        int b = b0 + half * 8 + rr;
        out[((size_t)b * SEQ + t) * OUTD + col] = e / denom;
    }
}

/* ------------------- host: two-stream fork/join pipeline --------------------- */
extern "C" void kernel_launch(void* const* d_in, const int* in_sizes, int n_in,
                              void* d_out, int out_size) {
    const float* x            = (const float*)d_in[0];
    const float* y            = (const float*)d_in[1];
    const float* memory       = (const float*)d_in[2];
    const float* read_weight  = (const float*)d_in[3];
    const float* usage_weight = (const float*)d_in[4];
    const float* Wl           = (const float*)d_in[5];
    const float* bl           = (const float*)d_in[6];
    const float* Wm           = (const float*)d_in[7];
    const float* bm           = (const float*)d_in[8];
    const float* Wf           = (const float*)d_in[9];
    const float* bf           = (const float*)d_in[10];
    const float* alpha        = (const float*)d_in[11];
    float* out = (float*)d_out;

    static cudaStream_t s1;
    static cudaEvent_t evFork, evJoin, evQ[SEQ];
    static int inited = 0;
    if (!inited) {
        cudaStreamCreateWithFlags(&s1, cudaStreamNonBlocking);
        cudaEventCreateWithFlags(&evFork, cudaEventDisableTiming);
        cudaEventCreateWithFlags(&evJoin, cudaEventDisableTiming);
        for (int t = 0; t < SEQ; t++)
            cudaEventCreateWithFlags(&evQ[t], cudaEventDisableTiming);
        cudaFuncSetAttribute(k_final, cudaFuncAttributeMaxDynamicSharedMemorySize,
                             (16 * OUTW + 128) * (int)sizeof(float));
        inited = 1;
    }

    cudaMemcpyToSymbolAsync(g_mem, memory, sizeof(float) * (size_t)BS * NSLOT * MDIM, 0,
                            cudaMemcpyDeviceToDevice, 0);
    cudaMemcpyToSymbolAsync(g_rw, read_weight, sizeof(float) * BS * RHEADS * NSLOT, 0,
                            cudaMemcpyDeviceToDevice, 0);
    cudaMemcpyToSymbolAsync(g_uw, usage_weight, sizeof(float) * BS * NSLOT, 0,
                            cudaMemcpyDeviceToDevice, 0);
    k_init<<<(BS * H + 255) / 256, 256>>>(alpha);
    k_select0<<<BS, 256>>>();

    cudaEventRecord(evFork, 0);
    cudaStreamWaitEvent(s1, evFork, 0);

    /* controller chain on s1 */
    k_zx<<<dim3(32, 1), 256, 0, s1>>>(x, y, Wl, bl, 0);
    k_rec<<<dim3(32, KSPL), 256, 0, s1>>>(Wl);
    k_gates<<<(BS * H) / 256, 256, 0, s1>>>(0);
    k_query<<<dim3(8, KSPL), 256, 0, s1>>>(Wm);
    k_qcomb<<<(BS * QW + 255) / 256, 256, 0, s1>>>(bm, 0);
    cudaEventRecord(evQ[0], s1);
    k_zx<<<dim3(32, SEQ - 1), 256, 0, s1>>>(x, y, Wl, bl, 1);
    for (int t = 1; t < SEQ; t++) {
        k_rec<<<dim3(32, KSPL), 256, 0, s1>>>(Wl);
        k_gates<<<(BS * H) / 256, 256, 0, s1>>>(t);
        k_query<<<dim3(8, KSPL), 256, 0, s1>>>(Wm);
        k_qcomb<<<(BS * QW + 255) / 256, 256, 0, s1>>>(bm, t);
        cudaEventRecord(evQ[t], s1);
    }
    cudaEventRecord(evJoin, s1);

    /* memory chain on capture stream */
    for (int t = 0; t < SEQ; t++) {
        cudaStreamWaitEvent(0, evQ[t], 0);
        k_memupd<<<dim3(16, BS), 256>>>(t);
        k_softmax_uw_sel<<<BS, 512>>>();
    }
    cudaStreamWaitEvent(0, evJoin, 0);

    size_t np = (size_t)BS * SEQ * OUTD;
    size_t nm = (size_t)BS * NSLOT * MDIM;
    size_t nr = (size_t)BS * RHEADS * NSLOT;
    k_memcopy_rv<<<dim3(16, BS), 256>>>(out + np);
    cudaMemcpyFromSymbolAsync(out + np + nm, g_rw, nr * sizeof(float), 0,
                              cudaMemcpyDeviceToDevice, 0);
    cudaMemcpyFromSymbolAsync(out + np + nm + nr, g_uw, (size_t)BS * NSLOT * sizeof(float), 0,
                              cudaMemcpyDeviceToDevice, 0);
    k_final<<<SEQ * BS / 16, 128, (16 * OUTW + 128) * sizeof(float)>>>(Wf, bf, out);
}

// round 9
// speedup vs baseline: 1.3077x; 1.0082x over previous
#include <cuda_runtime.h>
#include <math.h>
#include <float.h>

#define BS 64
#define SEQ 128
#define IN_DIM 256
#define H 512
#define NSLOT 4096
#define MDIM 128
#define RHEADS 4
#define OUTD 64
#define GAMMA_F 0.95f
#define JH (4 * H)               /* 2048 */
#define QW (RHEADS * MDIM)       /* 512  */
#define OUTW (H + RHEADS * MDIM) /* 1024 */
#define KSPL 8
#define RVCH 16

/* ------------------- persistent device state -------------------------------- */
__device__ float g_mem[(size_t)BS * NSLOT * MDIM];
__device__ float g_rw[BS * RHEADS * NSLOT];
__device__ float g_uw[BS * NSLOT];
__device__ float g_h[BS * H];
__device__ float g_c[BS * H];
__device__ float g_zx[(size_t)SEQ * BS * JH];
__device__ float g_zpart[KSPL * BS * JH];
__device__ float g_qpart[KSPL * BS * QW];
__device__ float g_qall[(size_t)SEQ * BS * QW];
__device__ int   g_idx[BS * RHEADS];
__device__ float g_alpha_s[BS * RHEADS];
__device__ float g_logits[BS * RHEADS * NSLOT];
__device__ float g_lmax[BS * RVCH * RHEADS];
__device__ float g_wwsum[BS * NSLOT];
__device__ float g_hist_h[(size_t)SEQ * BS * H];
__device__ float g_rvpart[(size_t)SEQ * RVCH * BS * QW];
__device__ float g_normQb[BS];
__device__ float g_normM_part[BS * 16];

__device__ __forceinline__ float sigmoidf_(float v) { return 1.f / (1.f + expf(-v)); }

/* ------------------- init ---------------------------------------------------- */
__global__ void k_init(const float* __restrict__ alpha) {
    int i = blockIdx.x * 256 + threadIdx.x;
    if (i < BS * H) { g_h[i] = 0.f; g_c[i] = 0.f; }
    if (i < BS * RHEADS) g_alpha_s[i] = sigmoidf_(alpha[i]);
}

/* ------------------- zx precompute ------------------------------------------ */
__global__ void k_zx(const float* __restrict__ x, const float* __restrict__ y,
                     const float* __restrict__ Wl, const float* __restrict__ bl, int t0) {
    __shared__ float s_in[16][68];
    int tid = threadIdx.x;
    int tj = tid & 15, tb = tid >> 4;
    int j0 = blockIdx.x * 64;
    int t  = blockIdx.y + t0;
    float acc[4][4];
#pragma unroll
    for (int i = 0; i < 4; i++)
#pragma unroll
        for (int jj = 0; jj < 4; jj++) acc[i][jj] = 0.f;

    for (int k0 = 0; k0 < IN_DIM; k0 += 16) {
        for (int l = tid; l < 1024; l += 256) {
            int kk = l & 15, b = l >> 4;
            s_in[kk][b] = x[((size_t)b * SEQ + t) * IN_DIM + k0 + kk];
        }
        __syncthreads();
#pragma unroll 4
        for (int kk = 0; kk < 16; kk++) {
            float4 av = *reinterpret_cast<const float4*>(&s_in[kk][tb * 4]);
            float4 wv = *reinterpret_cast<const float4*>(&Wl[(size_t)(k0 + kk) * JH + j0 + tj * 4]);
            const float* a = (const float*)&av;
            const float* w = (const float*)&wv;
#pragma unroll
            for (int bi = 0; bi < 4; bi++)
#pragma unroll
                for (int ji = 0; ji < 4; ji++) acc[bi][ji] += a[bi] * w[ji];
        }
        __syncthreads();
    }
    float4 bv = *reinterpret_cast<const float4*>(&bl[j0 + tj * 4]);
    float4 wy = *reinterpret_cast<const float4*>(&Wl[(size_t)IN_DIM * JH + j0 + tj * 4]);
    const float* bb = (const float*)&bv;
    const float* wyp = (const float*)&wy;
#pragma unroll
    for (int bi = 0; bi < 4; bi++) {
        int b = tb * 4 + bi;
        float yb = (t > 0) ? y[b * SEQ + t - 1] : 0.f;
        float4 o;
        o.x = acc[bi][0] + bb[0] + yb * wyp[0];
        o.y = acc[bi][1] + bb[1] + yb * wyp[1];
        o.z = acc[bi][2] + bb[2] + yb * wyp[2];
        o.w = acc[bi][3] + bb[3] + yb * wyp[3];
        *reinterpret_cast<float4*>(&g_zx[((size_t)t * BS + b) * JH + j0 + tj * 4]) = o;
    }
}

/* ------------------- recurrent GEMM partial --------------------------------- */
__global__ void k_rec(const float* __restrict__ Wl) {
    __shared__ float s_in[16][68];
    int tid = threadIdx.x;
    int tj = tid & 15, tb = tid >> 4;
    int j0 = blockIdx.x * 64;
    int s  = blockIdx.y;
    int kbase = s * (H / KSPL);
    float acc[4][4];
#pragma unroll
    for (int i = 0; i < 4; i++)
#pragma unroll
        for (int jj = 0; jj < 4; jj++) acc[i][jj] = 0.f;

    for (int k0 = 0; k0 < H / KSPL; k0 += 16) {
        for (int l = tid; l < 1024; l += 256) {
            int kk = l & 15, b = l >> 4;
            s_in[kk][b] = g_h[b * H + kbase + k0 + kk];
        }
        __syncthreads();
#pragma unroll 4
        for (int kk = 0; kk < 16; kk++) {
            float4 av = *reinterpret_cast<const float4*>(&s_in[kk][tb * 4]);
            float4 wv = *reinterpret_cast<const float4*>(
                &Wl[(size_t)(IN_DIM + 1 + kbase + k0 + kk) * JH + j0 + tj * 4]);
            const float* a = (const float*)&av;
            const float* w = (const float*)&wv;
#pragma unroll
            for (int bi = 0; bi < 4; bi++)
#pragma unroll
                for (int ji = 0; ji < 4; ji++) acc[bi][ji] += a[bi] * w[ji];
        }
        __syncthreads();
    }
#pragma unroll
    for (int bi = 0; bi < 4; bi++) {
        int b = tb * 4 + bi;
        float4 o;
        o.x = acc[bi][0]; o.y = acc[bi][1]; o.z = acc[bi][2]; o.w = acc[bi][3];
        *reinterpret_cast<float4*>(&g_zpart[((size_t)s * BS + b) * JH + j0 + tj * 4]) = o;
    }
}

/* ------------------- gates --------------------------------------------------- */
__global__ void k_gates(int t) {
    int i = blockIdx.x * 256 + threadIdx.x;
    if (i >= BS * H) return;
    int b = i / H, hh = i % H;
    size_t zbase = ((size_t)t * BS + b) * JH;
    float zg[4];
#pragma unroll
    for (int g = 0; g < 4; g++) {
        float v = g_zx[zbase + g * H + hh];
#pragma unroll
        for (int s = 0; s < KSPL; s++)
            v += g_zpart[((size_t)s * BS + b) * JH + g * H + hh];
        zg[g] = v;
    }
    float f  = sigmoidf_(zg[0]);
    float ig = sigmoidf_(zg[1]);
    float o  = sigmoidf_(zg[2]);
    float u  = tanhf(zg[3]);
    float c  = f * g_c[i] + ig * u;
    float h  = o * tanhf(c);
    g_c[i] = c; g_h[i] = h;
    g_hist_h[((size_t)t * BS + b) * H + hh] = h;
}

/* ------------------- query GEMM partial -------------------------------------- */
__global__ void k_query(const float* __restrict__ Wm) {
    __shared__ float s_in[16][68];
    int tid = threadIdx.x;
    int tj = tid & 15, tb = tid >> 4;
    int j0 = blockIdx.x * 64;
    int s  = blockIdx.y;
    int kbase = s * (H / KSPL);
    float acc[4][4];
#pragma unroll
    for (int i = 0; i < 4; i++)
#pragma unroll
        for (int jj = 0; jj < 4; jj++) acc[i][jj] = 0.f;

    for (int k0 = 0; k0 < H / KSPL; k0 += 16) {
        for (int l = tid; l < 1024; l += 256) {
            int kk = l & 15, b = l >> 4;
            s_in[kk][b] = g_h[b * H + kbase + k0 + kk];
        }
        __syncthreads();
#pragma unroll 4
        for (int kk = 0; kk < 16; kk++) {
            float4 av = *reinterpret_cast<const float4*>(&s_in[kk][tb * 4]);
            float4 wv = *reinterpret_cast<const float4*>(
                &Wm[(size_t)(kbase + k0 + kk) * QW + j0 + tj * 4]);
            const float* a = (const float*)&av;
            const float* w = (const float*)&wv;
#pragma unroll
            for (int bi = 0; bi < 4; bi++)
#pragma unroll
                for (int ji = 0; ji < 4; ji++) acc[bi][ji] += a[bi] * w[ji];
        }
        __syncthreads();
    }
#pragma unroll
    for (int bi = 0; bi < 4; bi++) {
        int b = tb * 4 + bi;
        float4 o;
        o.x = acc[bi][0]; o.y = acc[bi][1]; o.z = acc[bi][2]; o.w = acc[bi][3];
        *reinterpret_cast<float4*>(&g_qpart[((size_t)s * BS + b) * QW + j0 + tj * 4]) = o;
    }
}

/* ------------------- combine q partials -------------------------------------- */
__global__ void k_qcomb(const float* __restrict__ bm, int t) {
    int l = blockIdx.x * 256 + threadIdx.x;
    if (l >= BS * QW) return;
    int b = l >> 9, j = l & 511;
    float v = bm[j];
#pragma unroll
    for (int s = 0; s < KSPL; s++) v += g_qpart[((size_t)s * BS + b) * QW + j];
    g_qall[((size_t)t * BS + b) * QW + j] = v;
}

/* ------------------- initial select ------------------------------------------ */
__global__ void k_select0() {
    int b = blockIdx.x;
    int tid = threadIdx.x;
    __shared__ float sv[256];
    __shared__ int   si[256];
    __shared__ int   picked[RHEADS];
    const float* uw = &g_uw[(size_t)b * NSLOT];
    for (int r = 0; r < RHEADS; r++) {
        float bestv = FLT_MAX;
        int besti = 0x7fffffff;
        for (int n = tid; n < NSLOT; n += 256) {
            bool skip = false;
            for (int p = 0; p < r; p++) if (picked[p] == n) skip = true;
            if (skip) continue;
            float v = uw[n];
            if (v < bestv || (v == bestv && n < besti)) { bestv = v; besti = n; }
        }
        sv[tid] = bestv; si[tid] = besti;
        __syncthreads();
        for (int s = 128; s > 0; s >>= 1) {
            if (tid < s) {
                if (sv[tid + s] < sv[tid] || (sv[tid + s] == sv[tid] && si[tid + s] < si[tid])) {
                    sv[tid] = sv[tid + s]; si[tid] = si[tid + s];
                }
            }
            __syncthreads();
        }
        if (tid == 0) { picked[r] = si[0]; g_idx[b * RHEADS + r] = si[0]; }
        __syncthreads();
    }
}

/* ------------------- memupd(t): R8 body + one-stage load prefetch ------------ */
__global__ void k_memupd(int t) {
    int b  = blockIdx.y;
    int n0 = blockIdx.x * 256;
    __shared__ float sq[RHEADS][MDIM];
    __shared__ float srw[RHEADS][256];
    __shared__ float sal[RHEADS];
    __shared__ int   sidx[RHEADS];
    __shared__ float sredn[8];
    __shared__ float smax[8][RHEADS];
    __shared__ float s_red[256];
    __shared__ float sacc[8][QW];
    int tid = threadIdx.x;

    for (int l = tid; l < QW; l += 256)
        sq[l >> 7][l & 127] = g_qall[((size_t)t * BS + b) * QW + l];
    for (int l = tid; l < RHEADS * 256; l += 256) {
        int r = l >> 8, nn = l & 255;
        srw[r][nn] = g_rw[((size_t)b * RHEADS + r) * NSLOT + n0 + nn];
    }
    if (tid < RHEADS) { sal[tid] = g_alpha_s[b * RHEADS + tid]; sidx[tid] = g_idx[b * RHEADS + tid]; }
    __syncthreads();

    if (blockIdx.x == 0) {
        float local = 0.f;
        for (int l = tid; l < QW; l += 256) {
            float v = sq[l >> 7][l & 127];
            local += v * v;
        }
        s_red[tid] = local;
        __syncthreads();
        for (int s = 128; s > 0; s >>= 1) {
            if (tid < s) s_red[tid] += s_red[tid + s];
            __syncthreads();
        }
        if (tid == 0) g_normQb[b] = s_red[0];
        __syncthreads();
    }

    int warp = tid >> 5, lane = tid & 31;
    float normp = 0.f;
    float m0 = -FLT_MAX, m1 = -FLT_MAX, m2 = -FLT_MAX, m3 = -FLT_MAX;
    float rva[RHEADS][4];
#pragma unroll
    for (int r = 0; r < RHEADS; r++)
#pragma unroll
        for (int c = 0; c < 4; c++) rva[r][c] = 0.f;

    /* one-stage prefetch: next row's float4 is in flight while current row
       computes. Only +4 live registers; arithmetic identical to R8.         */
    float4 v = *reinterpret_cast<const float4*>(
        &g_mem[((size_t)b * NSLOT + n0 + warp) * MDIM + lane * 4]);
    for (int row = warp; row < 256; row += 8) {
        int n = n0 + row;
        float4 vnext;
        if (row + 8 < 256)
            vnext = *reinterpret_cast<const float4*>(
                &g_mem[((size_t)b * NSLOT + n + 8) * MDIM + lane * 4]);
        float r0w = srw[0][row], r1w = srw[1][row], r2w = srw[2][row], r3w = srw[3][row];
        float w0 = sal[0] * r0w; if (n == sidx[0]) w0 += 1.f - sal[0];
        float w1 = sal[1] * r1w; if (n == sidx[1]) w1 += 1.f - sal[1];
        float w2 = sal[2] * r2w; if (n == sidx[2]) w2 += 1.f - sal[2];
        float w3 = sal[3] * r3w; if (n == sidx[3]) w3 += 1.f - sal[3];
        float* vv = (float*)&v;
        float d0 = 0.f, d1 = 0.f, d2 = 0.f, d3 = 0.f;
#pragma unroll
        for (int cpt = 0; cpt < 4; cpt++) {
            int m = lane * 4 + cpt;
            float pre = vv[cpt];
            rva[0][cpt] += r0w * pre; rva[1][cpt] += r1w * pre;
            rva[2][cpt] += r2w * pre; rva[3][cpt] += r3w * pre;
            float q0 = sq[0][m], q1 = sq[1][m], q2 = sq[2][m], q3 = sq[3][m];
            float nv = pre + w0 * q0 + w1 * q1 + w2 * q2 + w3 * q3;
            d0 += q0 * nv; d1 += q1 * nv; d2 += q2 * nv; d3 += q3 * nv;
            normp += nv * nv;
            vv[cpt] = nv;
        }
        *reinterpret_cast<float4*>(
            &g_mem[((size_t)b * NSLOT + n) * MDIM + lane * 4]) = v;
#pragma unroll
        for (int off = 16; off > 0; off >>= 1) {
            d0 += __shfl_down_sync(0xffffffffu, d0, off);
            d1 += __shfl_down_sync(0xffffffffu, d1, off);
            d2 += __shfl_down_sync(0xffffffffu, d2, off);
            d3 += __shfl_down_sync(0xffffffffu, d3, off);
        }
        if (lane == 0) {
            g_logits[((size_t)b * RHEADS + 0) * NSLOT + n] = d0;
            g_logits[((size_t)b * RHEADS + 1) * NSLOT + n] = d1;
            g_logits[((size_t)b * RHEADS + 2) * NSLOT + n] = d2;
            g_logits[((size_t)b * RHEADS + 3) * NSLOT + n] = d3;
            g_wwsum[(size_t)b * NSLOT + n] = w0 + w1 + w2 + w3;
            m0 = fmaxf(m0, d0); m1 = fmaxf(m1, d1);
            m2 = fmaxf(m2, d2); m3 = fmaxf(m3, d3);
        }
        v = vnext;
    }
#pragma unroll
    for (int off = 16; off > 0; off >>= 1) normp += __shfl_down_sync(0xffffffffu, normp, off);
    if (lane == 0) {
        sredn[warp] = normp;
        smax[warp][0] = m0; smax[warp][1] = m1; smax[warp][2] = m2; smax[warp][3] = m3;
    }

#pragma unroll
    for (int r = 0; r < RHEADS; r++)
#pragma unroll
        for (int c = 0; c < 4; c++) sacc[warp][r * MDIM + lane * 4 + c] = rva[r][c];
    __syncthreads();

    if (tid == 0) {
        float s = 0.f;
        for (int i = 0; i < 8; i++) s += sredn[i];
        g_normM_part[b * 16 + blockIdx.x] = s;
    }
    if (tid < RHEADS) {
        float mm = smax[0][tid];
#pragma unroll
        for (int w = 1; w < 8; w++) mm = fmaxf(mm, smax[w][tid]);
        g_lmax[((size_t)b * RVCH + blockIdx.x) * RHEADS + tid] = mm;
    }
    if (t > 0) {
        for (int l = tid; l < QW; l += 256) {
            float s = 0.f;
#pragma unroll
            for (int w = 0; w < 8; w++) s += sacc[w][l];
            g_rvpart[(((size_t)(t - 1) * RVCH + blockIdx.x) * BS + b) * QW + l] = s;
        }
    }
}

/* ------------------- fused softmax + uw + select, float4 everywhere ---------- */
__global__ void k_softmax_uw_sel() {
    int b = blockIdx.x, tid = threadIdx.x;
    __shared__ float red[512];
    __shared__ float suw[NSLOT];
    __shared__ float s4v[512][4];
    __shared__ int   s4i[512][4];
    __shared__ float s_invscale;

    float lm = g_normM_part[tid] + g_normM_part[tid + 512];
    red[tid] = lm;
    __syncthreads();
    for (int s = 256; s > 0; s >>= 1) {
        if (tid < s) red[tid] += red[tid + s];
        __syncthreads();
    }
    float nm = red[0];
    __syncthreads();
    red[tid] = (tid < BS) ? g_normQb[tid] : 0.f;
    __syncthreads();
    for (int s = 256; s > 0; s >>= 1) {
        if (tid < s) red[tid] += red[tid + s];
        __syncthreads();
    }
    if (tid == 0) s_invscale = 1.f / (sqrtf(red[0]) * sqrtf(nm));
    __syncthreads();
    float invs = s_invscale;

    int g = tid >> 7, lt = tid & 127;
    const float4* lg4 = reinterpret_cast<const float4*>(
        &g_logits[((size_t)b * RHEADS + g) * NSLOT]);
    float4* rw4 = reinterpret_cast<float4*>(&g_rw[((size_t)b * RHEADS + g) * NSLOT]);

    float mxr = -FLT_MAX;
#pragma unroll
    for (int ch = 0; ch < RVCH; ch++)
        mxr = fmaxf(mxr, g_lmax[((size_t)b * RVCH + ch) * RHEADS + g]);
    float mx = mxr * invs;

    float4 e[8];
    float sum = 0.f;
#pragma unroll
    for (int i = 0; i < 8; i++) {
        float4 v = lg4[lt + i * 128];
        e[i].x = expf(v.x * invs - mx);
        e[i].y = expf(v.y * invs - mx);
        e[i].z = expf(v.z * invs - mx);
        e[i].w = expf(v.w * invs - mx);
        sum += e[i].x + e[i].y + e[i].z + e[i].w;
    }
    red[tid] = sum;
    __syncthreads();
    for (int s = 64; s > 0; s >>= 1) {
        if (lt < s) red[tid] += red[tid + s];
        __syncthreads();
    }
    float inv = 1.f / red[g << 7];
    __syncthreads();
#pragma unroll
    for (int i = 0; i < 8; i++) {
        float4 o;
        o.x = e[i].x * inv; o.y = e[i].y * inv;
        o.z = e[i].z * inv; o.w = e[i].w * inv;
        rw4[lt + i * 128] = o;
    }
    __syncthreads();

    {
        size_t base = (size_t)b * RHEADS * NSLOT;
        const float4* rwB = reinterpret_cast<const float4*>(&g_rw[base]);
        const float4* wwB = reinterpret_cast<const float4*>(&g_wwsum[(size_t)b * NSLOT]);
        float4* uwB = reinterpret_cast<float4*>(&g_uw[(size_t)b * NSLOT]);
        float4* suw4 = reinterpret_cast<float4*>(suw);
        const int NQ = NSLOT / 4;
#pragma unroll
        for (int it = 0; it < 2; it++) {
            int n4 = tid + it * 512;
            float4 r0 = rwB[n4];
            float4 r1 = rwB[NQ + n4];
            float4 r2 = rwB[2 * NQ + n4];
            float4 r3 = rwB[3 * NQ + n4];
            float4 ww = wwB[n4];
            float4 uo = uwB[n4];
            float4 u;
            u.x = GAMMA_F * uo.x + (r0.x + r1.x + r2.x + r3.x) + ww.x;
            u.y = GAMMA_F * uo.y + (r0.y + r1.y + r2.y + r3.y) + ww.y;
            u.z = GAMMA_F * uo.z + (r0.z + r1.z + r2.z + r3.z) + ww.z;
            u.w = GAMMA_F * uo.w + (r0.w + r1.w + r2.w + r3.w) + ww.w;
            uwB[n4] = u;
            suw4[n4] = u;
        }
    }
    __syncthreads();

    float tv[4]; int ti[4];
#pragma unroll
    for (int k = 0; k < 4; k++) { tv[k] = FLT_MAX; ti[k] = 0x7fffffff; }
    for (int n = tid; n < NSLOT; n += 512) {
        float v = suw[n];
        if (v < tv[3] || (v == tv[3] && n < ti[3])) {
            int k = 3;
            while (k > 0 && (v < tv[k - 1] || (v == tv[k - 1] && n < ti[k - 1]))) {
                tv[k] = tv[k - 1]; ti[k] = ti[k - 1]; k--;
            }
            tv[k] = v; ti[k] = n;
        }
    }
#pragma unroll
    for (int k = 0; k < 4; k++) { s4v[tid][k] = tv[k]; s4i[tid][k] = ti[k]; }
    __syncthreads();

    for (int s = 256; s > 0; s >>= 1) {
        if (tid < s) {
            float av[4], bv[4], ov[4];
            int ai[4], bi[4], oi[4];
#pragma unroll
            for (int k = 0; k < 4; k++) {
                av[k] = s4v[tid][k];     ai[k] = s4i[tid][k];
                bv[k] = s4v[tid + s][k]; bi[k] = s4i[tid + s][k];
            }
            int a = 0, c = 0;
#pragma unroll
            for (int k = 0; k < 4; k++) {
                bool takeA = (av[a] < bv[c]) || (av[a] == bv[c] && ai[a] < bi[c]);
                if (takeA) { ov[k] = av[a]; oi[k] = ai[a]; a++; }
                else       { ov[k] = bv[c]; oi[k] = bi[c]; c++; }
            }
#pragma unroll
            for (int k = 0; k < 4; k++) { s4v[tid][k] = ov[k]; s4i[tid][k] = oi[k]; }
        }
        __syncthreads();
    }
    if (tid < RHEADS) g_idx[b * RHEADS + tid] = s4i[0][tid];
}

/* ------------------- final mem copy-out + readvec(SEQ-1) --------------------- */
__global__ void k_memcopy_rv(float* __restrict__ out_mem) {
    int b  = blockIdx.y;
    int n0 = blockIdx.x * 256;
    int tid = threadIdx.x;
    int warp = tid >> 5, lane = tid & 31;
    __shared__ float srw[RHEADS][256];
    __shared__ float sacc[8][QW];

    for (int l = tid; l < RHEADS * 256; l += 256) {
        int r = l >> 8, nn = l & 255;
        srw[r][nn] = g_rw[((size_t)b * RHEADS + r) * NSLOT + n0 + nn];
    }
    __syncthreads();

    float rva[RHEADS][4];
#pragma unroll
    for (int r = 0; r < RHEADS; r++)
#pragma unroll
        for (int c = 0; c < 4; c++) rva[r][c] = 0.f;

    for (int row = warp; row < 256; row += 8) {
        int n = n0 + row;
        size_t off = ((size_t)b * NSLOT + n) * MDIM + lane * 4;
        float4 v = *reinterpret_cast<const float4*>(&g_mem[off]);
        *reinterpret_cast<float4*>(&out_mem[off]) = v;
        const float* vv = (const float*)&v;
#pragma unroll
        for (int r = 0; r < RHEADS; r++) {
            float w = srw[r][row];
#pragma unroll
            for (int c = 0; c < 4; c++) rva[r][c] += w * vv[c];
        }
    }
#pragma unroll
    for (int r = 0; r < RHEADS; r++)
#pragma unroll
        for (int c = 0; c < 4; c++) sacc[warp][r * MDIM + lane * 4 + c] = rva[r][c];
    __syncthreads();
    for (int l = tid; l < QW; l += 256) {
        float s = 0.f;
#pragma unroll
        for (int w = 0; w < 8; w++) s += sacc[w][l];
        g_rvpart[(((size_t)(SEQ - 1) * RVCH + blockIdx.x) * BS + b) * QW + l] = s;
    }
}

/* ------------------- final projection + softmax ------------------------------ */
__global__ void k_final(const float* __restrict__ Wf, const float* __restrict__ bf,
                        float* __restrict__ out) {
    extern __shared__ float sm[];
    float (*svv)[OUTW] = (float (*)[OUTW])sm;
    float* red = sm + 16 * OUTW;
    int tid = threadIdx.x;
    int r0 = blockIdx.x * 16;
    int t  = r0 / BS;
    int b0 = r0 % BS;

    for (int l = tid; l < 16 * H; l += 128) {
        int rr = l >> 9, k = l & 511;
        svv[rr][k] = g_hist_h[((size_t)(r0 + rr)) * H + k];
    }
    for (int l = tid; l < 16 * QW; l += 128) {
        int rr = l >> 9, k = l & 511;
        float s = 0.f;
#pragma unroll
        for (int c = 0; c < RVCH; c++)
            s += g_rvpart[(((size_t)t * RVCH + c) * BS + (b0 + rr)) * QW + k];
        svv[rr][H + k] = s;
    }
    __syncthreads();

    int half = tid >> 6, col = tid & 63;
    float accs[8];
#pragma unroll
    for (int rr = 0; rr < 8; rr++) accs[rr] = bf[col];
    for (int k = 0; k < OUTW; k++) {
        float w = Wf[(size_t)k * OUTD + col];
#pragma unroll
        for (int rr = 0; rr < 8; rr++) accs[rr] += svv[half * 8 + rr][k] * w;
    }
    for (int rr = 0; rr < 8; rr++) {
        red[tid] = accs[rr];
        __syncthreads();
        for (int s = 32; s > 0; s >>= 1) {
            if ((tid & 63) < s) red[tid] = fmaxf(red[tid], red[tid + s]);
            __syncthreads();
        }
        float mx = red[half * 64];
        __syncthreads();
        float e = expf(accs[rr] - mx);
        red[tid] = e;
        __syncthreads();
        for (int s = 32; s > 0; s >>= 1) {
            if ((tid & 63) < s) red[tid] += red[tid + s];
            __syncthreads();
        }
        float denom = red[half * 64];
        __syncthreads();
        int b = b0 + half * 8 + rr;
        out[((size_t)b * SEQ + t) * OUTD + col] = e / denom;
    }
}

/* ------------------- host: two-stream fork/join pipeline --------------------- */
extern "C" void kernel_launch(void* const* d_in, const int* in_sizes, int n_in,
                              void* d_out, int out_size) {
    const float* x            = (const float*)d_in[0];
    const float* y            = (const float*)d_in[1];
    const float* memory       = (const float*)d_in[2];
    const float* read_weight  = (const float*)d_in[3];
    const float* usage_weight = (const float*)d_in[4];
    const float* Wl           = (const float*)d_in[5];
    const float* bl           = (const float*)d_in[6];
    const float* Wm           = (const float*)d_in[7];
    const float* bm           = (const float*)d_in[8];
    const float* Wf           = (const float*)d_in[9];
    const float* bf           = (const float*)d_in[10];
    const float* alpha        = (const float*)d_in[11];
    float* out = (float*)d_out;

    static cudaStream_t s1;
    static cudaEvent_t evFork, evJoin, evQ[SEQ];
    static int inited = 0;
    if (!inited) {
        cudaStreamCreateWithFlags(&s1, cudaStreamNonBlocking);
        cudaEventCreateWithFlags(&evFork, cudaEventDisableTiming);
        cudaEventCreateWithFlags(&evJoin, cudaEventDisableTiming);
        for (int t = 0; t < SEQ; t++)
            cudaEventCreateWithFlags(&evQ[t], cudaEventDisableTiming);
        cudaFuncSetAttribute(k_final, cudaFuncAttributeMaxDynamicSharedMemorySize,
                             (16 * OUTW + 128) * (int)sizeof(float));
        inited = 1;
    }

    cudaMemcpyToSymbolAsync(g_mem, memory, sizeof(float) * (size_t)BS * NSLOT * MDIM, 0,
                            cudaMemcpyDeviceToDevice, 0);
    cudaMemcpyToSymbolAsync(g_rw, read_weight, sizeof(float) * BS * RHEADS * NSLOT, 0,
                            cudaMemcpyDeviceToDevice, 0);
    cudaMemcpyToSymbolAsync(g_uw, usage_weight, sizeof(float) * BS * NSLOT, 0,
                            cudaMemcpyDeviceToDevice, 0);
    k_init<<<(BS * H + 255) / 256, 256>>>(alpha);
    k_select0<<<BS, 256>>>();

    cudaEventRecord(evFork, 0);
    cudaStreamWaitEvent(s1, evFork, 0);

    /* controller chain on s1 */
    k_zx<<<dim3(32, 1), 256, 0, s1>>>(x, y, Wl, bl, 0);
    k_rec<<<dim3(32, KSPL), 256, 0, s1>>>(Wl);
    k_gates<<<(BS * H) / 256, 256, 0, s1>>>(0);
    k_query<<<dim3(8, KSPL), 256, 0, s1>>>(Wm);
    k_qcomb<<<(BS * QW + 255) / 256, 256, 0, s1>>>(bm, 0);
    cudaEventRecord(evQ[0], s1);
    k_zx<<<dim3(32, SEQ - 1), 256, 0, s1>>>(x, y, Wl, bl, 1);
    for (int t = 1; t < SEQ; t++) {
        k_rec<<<dim3(32, KSPL), 256, 0, s1>>>(Wl);
        k_gates<<<(BS * H) / 256, 256, 0, s1>>>(t);
        k_query<<<dim3(8, KSPL), 256, 0, s1>>>(Wm);
        k_qcomb<<<(BS * QW + 255) / 256, 256, 0, s1>>>(bm, t);
        cudaEventRecord(evQ[t], s1);
    }
    cudaEventRecord(evJoin, s1);

    /* memory chain on capture stream */
    for (int t = 0; t < SEQ; t++) {
        cudaStreamWaitEvent(0, evQ[t], 0);
        k_memupd<<<dim3(16, BS), 256>>>(t);
        k_softmax_uw_sel<<<BS, 512>>>();
    }
    cudaStreamWaitEvent(0, evJoin, 0);

    size_t np = (size_t)BS * SEQ * OUTD;
    size_t nm = (size_t)BS * NSLOT * MDIM;
    size_t nr = (size_t)BS * RHEADS * NSLOT;
    k_memcopy_rv<<<dim3(16, BS), 256>>>(out + np);
    cudaMemcpyFromSymbolAsync(out + np + nm, g_rw, nr * sizeof(float), 0,
                              cudaMemcpyDeviceToDevice, 0);
    cudaMemcpyFromSymbolAsync(out + np + nm + nr, g_uw, (size_t)BS * NSLOT * sizeof(float), 0,
                              cudaMemcpyDeviceToDevice, 0);
    k_final<<<SEQ * BS / 16, 128, (16 * OUTW + 128) * sizeof(float)>>>(Wf, bf, out);
}

// round 10
// speedup vs baseline: 1.3467x; 1.0298x over previous
#include <cuda_runtime.h>
#include <math.h>
#include <float.h>

#define BS 64
#define SEQ 128
#define IN_DIM 256
#define H 512
#define NSLOT 4096
#define MDIM 128
#define RHEADS 4
#define OUTD 64
#define GAMMA_F 0.95f
#define JH (4 * H)               /* 2048 */
#define QW (RHEADS * MDIM)       /* 512  */
#define OUTW (H + RHEADS * MDIM) /* 1024 */
#define KSPL 8
#define RVCH 8                   /* 512 blocks -> single resident wave */
#define RPB 512                  /* rows per memupd block */

/* ------------------- persistent device state -------------------------------- */
__device__ float g_mem[(size_t)BS * NSLOT * MDIM];
__device__ float g_rw[BS * RHEADS * NSLOT];
__device__ float g_uw[BS * NSLOT];
__device__ float g_h[BS * H];
__device__ float g_c[BS * H];
__device__ float g_zx[(size_t)SEQ * BS * JH];
__device__ float g_zpart[KSPL * BS * JH];
__device__ float g_qpart[KSPL * BS * QW];
__device__ float g_qall[(size_t)SEQ * BS * QW];
__device__ int   g_idx[BS * RHEADS];
__device__ float g_alpha_s[BS * RHEADS];
__device__ float g_logits[BS * RHEADS * NSLOT];
__device__ float g_lmax[BS * RVCH * RHEADS];
__device__ float g_wwsum[BS * NSLOT];
__device__ float g_hist_h[(size_t)SEQ * BS * H];
__device__ float g_rvpart[(size_t)SEQ * RVCH * BS * QW];
__device__ float g_normQb[BS];
__device__ float g_normM_part[BS * RVCH];   /* 512 entries */

__device__ __forceinline__ float sigmoidf_(float v) { return 1.f / (1.f + expf(-v)); }

/* ------------------- init ---------------------------------------------------- */
__global__ void k_init(const float* __restrict__ alpha) {
    int i = blockIdx.x * 256 + threadIdx.x;
    if (i < BS * H) { g_h[i] = 0.f; g_c[i] = 0.f; }
    if (i < BS * RHEADS) g_alpha_s[i] = sigmoidf_(alpha[i]);
}

/* ------------------- zx precompute ------------------------------------------ */
__global__ void k_zx(const float* __restrict__ x, const float* __restrict__ y,
                     const float* __restrict__ Wl, const float* __restrict__ bl, int t0) {
    __shared__ float s_in[16][68];
    int tid = threadIdx.x;
    int tj = tid & 15, tb = tid >> 4;
    int j0 = blockIdx.x * 64;
    int t  = blockIdx.y + t0;
    float acc[4][4];
#pragma unroll
    for (int i = 0; i < 4; i++)
#pragma unroll
        for (int jj = 0; jj < 4; jj++) acc[i][jj] = 0.f;

    for (int k0 = 0; k0 < IN_DIM; k0 += 16) {
        for (int l = tid; l < 1024; l += 256) {
            int kk = l & 15, b = l >> 4;
            s_in[kk][b] = x[((size_t)b * SEQ + t) * IN_DIM + k0 + kk];
        }
        __syncthreads();
#pragma unroll 4
        for (int kk = 0; kk < 16; kk++) {
            float4 av = *reinterpret_cast<const float4*>(&s_in[kk][tb * 4]);
            float4 wv = *reinterpret_cast<const float4*>(&Wl[(size_t)(k0 + kk) * JH + j0 + tj * 4]);
            const float* a = (const float*)&av;
            const float* w = (const float*)&wv;
#pragma unroll
            for (int bi = 0; bi < 4; bi++)
#pragma unroll
                for (int ji = 0; ji < 4; ji++) acc[bi][ji] += a[bi] * w[ji];
        }
        __syncthreads();
    }
    float4 bv = *reinterpret_cast<const float4*>(&bl[j0 + tj * 4]);
    float4 wy = *reinterpret_cast<const float4*>(&Wl[(size_t)IN_DIM * JH + j0 + tj * 4]);
    const float* bb = (const float*)&bv;
    const float* wyp = (const float*)&wy;
#pragma unroll
    for (int bi = 0; bi < 4; bi++) {
        int b = tb * 4 + bi;
        float yb = (t > 0) ? y[b * SEQ + t - 1] : 0.f;
        float4 o;
        o.x = acc[bi][0] + bb[0] + yb * wyp[0];
        o.y = acc[bi][1] + bb[1] + yb * wyp[1];
        o.z = acc[bi][2] + bb[2] + yb * wyp[2];
        o.w = acc[bi][3] + bb[3] + yb * wyp[3];
        *reinterpret_cast<float4*>(&g_zx[((size_t)t * BS + b) * JH + j0 + tj * 4]) = o;
    }
}

/* ------------------- recurrent GEMM partial --------------------------------- */
__global__ void k_rec(const float* __restrict__ Wl) {
    __shared__ float s_in[16][68];
    int tid = threadIdx.x;
    int tj = tid & 15, tb = tid >> 4;
    int j0 = blockIdx.x * 64;
    int s  = blockIdx.y;
    int kbase = s * (H / KSPL);
    float acc[4][4];
#pragma unroll
    for (int i = 0; i < 4; i++)
#pragma unroll
        for (int jj = 0; jj < 4; jj++) acc[i][jj] = 0.f;

    for (int k0 = 0; k0 < H / KSPL; k0 += 16) {
        for (int l = tid; l < 1024; l += 256) {
            int kk = l & 15, b = l >> 4;
            s_in[kk][b] = g_h[b * H + kbase + k0 + kk];
        }
        __syncthreads();
#pragma unroll 4
        for (int kk = 0; kk < 16; kk++) {
            float4 av = *reinterpret_cast<const float4*>(&s_in[kk][tb * 4]);
            float4 wv = *reinterpret_cast<const float4*>(
                &Wl[(size_t)(IN_DIM + 1 + kbase + k0 + kk) * JH + j0 + tj * 4]);
            const float* a = (const float*)&av;
            const float* w = (const float*)&wv;
#pragma unroll
            for (int bi = 0; bi < 4; bi++)
#pragma unroll
                for (int ji = 0; ji < 4; ji++) acc[bi][ji] += a[bi] * w[ji];
        }
        __syncthreads();
    }
#pragma unroll
    for (int bi = 0; bi < 4; bi++) {
        int b = tb * 4 + bi;
        float4 o;
        o.x = acc[bi][0]; o.y = acc[bi][1]; o.z = acc[bi][2]; o.w = acc[bi][3];
        *reinterpret_cast<float4*>(&g_zpart[((size_t)s * BS + b) * JH + j0 + tj * 4]) = o;
    }
}

/* ------------------- gates --------------------------------------------------- */
__global__ void k_gates(int t) {
    int i = blockIdx.x * 256 + threadIdx.x;
    if (i >= BS * H) return;
    int b = i / H, hh = i % H;
    size_t zbase = ((size_t)t * BS + b) * JH;
    float zg[4];
#pragma unroll
    for (int g = 0; g < 4; g++) {
        float v = g_zx[zbase + g * H + hh];
#pragma unroll
        for (int s = 0; s < KSPL; s++)
            v += g_zpart[((size_t)s * BS + b) * JH + g * H + hh];
        zg[g] = v;
    }
    float f  = sigmoidf_(zg[0]);
    float ig = sigmoidf_(zg[1]);
    float o  = sigmoidf_(zg[2]);
    float u  = tanhf(zg[3]);
    float c  = f * g_c[i] + ig * u;
    float h  = o * tanhf(c);
    g_c[i] = c; g_h[i] = h;
    g_hist_h[((size_t)t * BS + b) * H + hh] = h;
}

/* ------------------- query GEMM partial -------------------------------------- */
__global__ void k_query(const float* __restrict__ Wm) {
    __shared__ float s_in[16][68];
    int tid = threadIdx.x;
    int tj = tid & 15, tb = tid >> 4;
    int j0 = blockIdx.x * 64;
    int s  = blockIdx.y;
    int kbase = s * (H / KSPL);
    float acc[4][4];
#pragma unroll
    for (int i = 0; i < 4; i++)
#pragma unroll
        for (int jj = 0; jj < 4; jj++) acc[i][jj] = 0.f;

    for (int k0 = 0; k0 < H / KSPL; k0 += 16) {
        for (int l = tid; l < 1024; l += 256) {
            int kk = l & 15, b = l >> 4;
            s_in[kk][b] = g_h[b * H + kbase + k0 + kk];
        }
        __syncthreads();
#pragma unroll 4
        for (int kk = 0; kk < 16; kk++) {
            float4 av = *reinterpret_cast<const float4*>(&s_in[kk][tb * 4]);
            float4 wv = *reinterpret_cast<const float4*>(
                &Wm[(size_t)(kbase + k0 + kk) * QW + j0 + tj * 4]);
            const float* a = (const float*)&av;
            const float* w = (const float*)&wv;
#pragma unroll
            for (int bi = 0; bi < 4; bi++)
#pragma unroll
                for (int ji = 0; ji < 4; ji++) acc[bi][ji] += a[bi] * w[ji];
        }
        __syncthreads();
    }
#pragma unroll
    for (int bi = 0; bi < 4; bi++) {
        int b = tb * 4 + bi;
        float4 o;
        o.x = acc[bi][0]; o.y = acc[bi][1]; o.z = acc[bi][2]; o.w = acc[bi][3];
        *reinterpret_cast<float4*>(&g_qpart[((size_t)s * BS + b) * QW + j0 + tj * 4]) = o;
    }
}

/* ------------------- combine q partials -------------------------------------- */
__global__ void k_qcomb(const float* __restrict__ bm, int t) {
    int l = blockIdx.x * 256 + threadIdx.x;
    if (l >= BS * QW) return;
    int b = l >> 9, j = l & 511;
    float v = bm[j];
#pragma unroll
    for (int s = 0; s < KSPL; s++) v += g_qpart[((size_t)s * BS + b) * QW + j];
    g_qall[((size_t)t * BS + b) * QW + j] = v;
}

/* ------------------- initial select ------------------------------------------ */
__global__ void k_select0() {
    int b = blockIdx.x;
    int tid = threadIdx.x;
    __shared__ float sv[256];
    __shared__ int   si[256];
    __shared__ int   picked[RHEADS];
    const float* uw = &g_uw[(size_t)b * NSLOT];
    for (int r = 0; r < RHEADS; r++) {
        float bestv = FLT_MAX;
        int besti = 0x7fffffff;
        for (int n = tid; n < NSLOT; n += 256) {
            bool skip = false;
            for (int p = 0; p < r; p++) if (picked[p] == n) skip = true;
            if (skip) continue;
            float v = uw[n];
            if (v < bestv || (v == bestv && n < besti)) { bestv = v; besti = n; }
        }
        sv[tid] = bestv; si[tid] = besti;
        __syncthreads();
        for (int s = 128; s > 0; s >>= 1) {
            if (tid < s) {
                if (sv[tid + s] < sv[tid] || (sv[tid + s] == sv[tid] && si[tid + s] < si[tid])) {
                    sv[tid] = sv[tid + s]; si[tid] = si[tid + s];
                }
            }
            __syncthreads();
        }
        if (tid == 0) { picked[r] = si[0]; g_idx[b * RHEADS + r] = si[0]; }
        __syncthreads();
    }
}

/* ------------------- memupd(t): 512 rows/block, single resident wave --------- */
__global__ void k_memupd(int t) {
    int b  = blockIdx.y;
    int n0 = blockIdx.x * RPB;
    __shared__ float sq[RHEADS][MDIM];
    __shared__ float srw[RHEADS][RPB];
    __shared__ float sal[RHEADS];
    __shared__ int   sidx[RHEADS];
    __shared__ float sredn[8];
    __shared__ float smax[8][RHEADS];
    __shared__ float s_red[256];
    __shared__ float sacc[8][QW];
    int tid = threadIdx.x;

    for (int l = tid; l < QW; l += 256)
        sq[l >> 7][l & 127] = g_qall[((size_t)t * BS + b) * QW + l];
    for (int l = tid; l < RHEADS * RPB; l += 256) {
        int r = l / RPB, nn = l % RPB;
        srw[r][nn] = g_rw[((size_t)b * RHEADS + r) * NSLOT + n0 + nn];
    }
    if (tid < RHEADS) { sal[tid] = g_alpha_s[b * RHEADS + tid]; sidx[tid] = g_idx[b * RHEADS + tid]; }
    __syncthreads();

    if (blockIdx.x == 0) {
        float local = 0.f;
        for (int l = tid; l < QW; l += 256) {
            float v = sq[l >> 7][l & 127];
            local += v * v;
        }
        s_red[tid] = local;
        __syncthreads();
        for (int s = 128; s > 0; s >>= 1) {
            if (tid < s) s_red[tid] += s_red[tid + s];
            __syncthreads();
        }
        if (tid == 0) g_normQb[b] = s_red[0];
        __syncthreads();
    }

    int warp = tid >> 5, lane = tid & 31;
    float normp = 0.f;
    float m0 = -FLT_MAX, m1 = -FLT_MAX, m2 = -FLT_MAX, m3 = -FLT_MAX;
    float rva[RHEADS][4];
#pragma unroll
    for (int r = 0; r < RHEADS; r++)
#pragma unroll
        for (int c = 0; c < 4; c++) rva[r][c] = 0.f;

    float4 v = *reinterpret_cast<const float4*>(
        &g_mem[((size_t)b * NSLOT + n0 + warp) * MDIM + lane * 4]);
    for (int row = warp; row < RPB; row += 8) {
        int n = n0 + row;
        float4 vnext;
        if (row + 8 < RPB)
            vnext = *reinterpret_cast<const float4*>(
                &g_mem[((size_t)b * NSLOT + n + 8) * MDIM + lane * 4]);
        float r0w = srw[0][row], r1w = srw[1][row], r2w = srw[2][row], r3w = srw[3][row];
        float w0 = sal[0] * r0w; if (n == sidx[0]) w0 += 1.f - sal[0];
        float w1 = sal[1] * r1w; if (n == sidx[1]) w1 += 1.f - sal[1];
        float w2 = sal[2] * r2w; if (n == sidx[2]) w2 += 1.f - sal[2];
        float w3 = sal[3] * r3w; if (n == sidx[3]) w3 += 1.f - sal[3];
        float* vv = (float*)&v;
        float d0 = 0.f, d1 = 0.f, d2 = 0.f, d3 = 0.f;
#pragma unroll
        for (int cpt = 0; cpt < 4; cpt++) {
            int m = lane * 4 + cpt;
            float pre = vv[cpt];
            rva[0][cpt] += r0w * pre; rva[1][cpt] += r1w * pre;
            rva[2][cpt] += r2w * pre; rva[3][cpt] += r3w * pre;
            float q0 = sq[0][m], q1 = sq[1][m], q2 = sq[2][m], q3 = sq[3][m];
            float nv = pre + w0 * q0 + w1 * q1 + w2 * q2 + w3 * q3;
            d0 += q0 * nv; d1 += q1 * nv; d2 += q2 * nv; d3 += q3 * nv;
            normp += nv * nv;
            vv[cpt] = nv;
        }
        *reinterpret_cast<float4*>(
            &g_mem[((size_t)b * NSLOT + n) * MDIM + lane * 4]) = v;
#pragma unroll
        for (int off = 16; off > 0; off >>= 1) {
            d0 += __shfl_down_sync(0xffffffffu, d0, off);
            d1 += __shfl_down_sync(0xffffffffu, d1, off);
            d2 += __shfl_down_sync(0xffffffffu, d2, off);
            d3 += __shfl_down_sync(0xffffffffu, d3, off);
        }
        if (lane == 0) {
            g_logits[((size_t)b * RHEADS + 0) * NSLOT + n] = d0;
            g_logits[((size_t)b * RHEADS + 1) * NSLOT + n] = d1;
            g_logits[((size_t)b * RHEADS + 2) * NSLOT + n] = d2;
            g_logits[((size_t)b * RHEADS + 3) * NSLOT + n] = d3;
            g_wwsum[(size_t)b * NSLOT + n] = w0 + w1 + w2 + w3;
            m0 = fmaxf(m0, d0); m1 = fmaxf(m1, d1);
            m2 = fmaxf(m2, d2); m3 = fmaxf(m3, d3);
        }
        v = vnext;
    }
#pragma unroll
    for (int off = 16; off > 0; off >>= 1) normp += __shfl_down_sync(0xffffffffu, normp, off);
    if (lane == 0) {
        sredn[warp] = normp;
        smax[warp][0] = m0; smax[warp][1] = m1; smax[warp][2] = m2; smax[warp][3] = m3;
    }

#pragma unroll
    for (int r = 0; r < RHEADS; r++)
#pragma unroll
        for (int c = 0; c < 4; c++) sacc[warp][r * MDIM + lane * 4 + c] = rva[r][c];
    __syncthreads();

    if (tid == 0) {
        float s = 0.f;
        for (int i = 0; i < 8; i++) s += sredn[i];
        g_normM_part[b * RVCH + blockIdx.x] = s;
    }
    if (tid < RHEADS) {
        float mm = smax[0][tid];
#pragma unroll
        for (int w = 1; w < 8; w++) mm = fmaxf(mm, smax[w][tid]);
        g_lmax[((size_t)b * RVCH + blockIdx.x) * RHEADS + tid] = mm;
    }
    if (t > 0) {
        for (int l = tid; l < QW; l += 256) {
            float s = 0.f;
#pragma unroll
            for (int w = 0; w < 8; w++) s += sacc[w][l];
            g_rvpart[(((size_t)(t - 1) * RVCH + blockIdx.x) * BS + b) * QW + l] = s;
        }
    }
}

/* ------------------- fused softmax + uw + select, float4 everywhere ---------- */
__global__ void k_softmax_uw_sel() {
    int b = blockIdx.x, tid = threadIdx.x;
    __shared__ float red[512];
    __shared__ float suw[NSLOT];
    __shared__ float s4v[512][4];
    __shared__ int   s4i[512][4];
    __shared__ float s_invscale;

    /* global norms: 512 partials over 512 threads */
    red[tid] = g_normM_part[tid];
    __syncthreads();
    for (int s = 256; s > 0; s >>= 1) {
        if (tid < s) red[tid] += red[tid + s];
        __syncthreads();
    }
    float nm = red[0];
    __syncthreads();
    red[tid] = (tid < BS) ? g_normQb[tid] : 0.f;
    __syncthreads();
    for (int s = 256; s > 0; s >>= 1) {
        if (tid < s) red[tid] += red[tid + s];
        __syncthreads();
    }
    if (tid == 0) s_invscale = 1.f / (sqrtf(red[0]) * sqrtf(nm));
    __syncthreads();
    float invs = s_invscale;

    int g = tid >> 7, lt = tid & 127;
    const float4* lg4 = reinterpret_cast<const float4*>(
        &g_logits[((size_t)b * RHEADS + g) * NSLOT]);
    float4* rw4 = reinterpret_cast<float4*>(&g_rw[((size_t)b * RHEADS + g) * NSLOT]);

    float mxr = -FLT_MAX;
#pragma unroll
    for (int ch = 0; ch < RVCH; ch++)
        mxr = fmaxf(mxr, g_lmax[((size_t)b * RVCH + ch) * RHEADS + g]);
    float mx = mxr * invs;

    float4 e[8];
    float sum = 0.f;
#pragma unroll
    for (int i = 0; i < 8; i++) {
        float4 v = lg4[lt + i * 128];
        e[i].x = expf(v.x * invs - mx);
        e[i].y = expf(v.y * invs - mx);
        e[i].z = expf(v.z * invs - mx);
        e[i].w = expf(v.w * invs - mx);
        sum += e[i].x + e[i].y + e[i].z + e[i].w;
    }
    red[tid] = sum;
    __syncthreads();
    for (int s = 64; s > 0; s >>= 1) {
        if (lt < s) red[tid] += red[tid + s];
        __syncthreads();
    }
    float inv = 1.f / red[g << 7];
    __syncthreads();
#pragma unroll
    for (int i = 0; i < 8; i++) {
        float4 o;
        o.x = e[i].x * inv; o.y = e[i].y * inv;
        o.z = e[i].z * inv; o.w = e[i].w * inv;
        rw4[lt + i * 128] = o;
    }
    __syncthreads();

    {
        size_t base = (size_t)b * RHEADS * NSLOT;
        const float4* rwB = reinterpret_cast<const float4*>(&g_rw[base]);
        const float4* wwB = reinterpret_cast<const float4*>(&g_wwsum[(size_t)b * NSLOT]);
        float4* uwB = reinterpret_cast<float4*>(&g_uw[(size_t)b * NSLOT]);
        float4* suw4 = reinterpret_cast<float4*>(suw);
        const int NQ = NSLOT / 4;
#pragma unroll
        for (int it = 0; it < 2; it++) {
            int n4 = tid + it * 512;
            float4 r0 = rwB[n4];
            float4 r1 = rwB[NQ + n4];
            float4 r2 = rwB[2 * NQ + n4];
            float4 r3 = rwB[3 * NQ + n4];
            float4 ww = wwB[n4];
            float4 uo = uwB[n4];
            float4 u;
            u.x = GAMMA_F * uo.x + (r0.x + r1.x + r2.x + r3.x) + ww.x;
            u.y = GAMMA_F * uo.y + (r0.y + r1.y + r2.y + r3.y) + ww.y;
            u.z = GAMMA_F * uo.z + (r0.z + r1.z + r2.z + r3.z) + ww.z;
            u.w = GAMMA_F * uo.w + (r0.w + r1.w + r2.w + r3.w) + ww.w;
            uwB[n4] = u;
            suw4[n4] = u;
        }
    }
    __syncthreads();

    float tv[4]; int ti[4];
#pragma unroll
    for (int k = 0; k < 4; k++) { tv[k] = FLT_MAX; ti[k] = 0x7fffffff; }
    for (int n = tid; n < NSLOT; n += 512) {
        float v = suw[n];
        if (v < tv[3] || (v == tv[3] && n < ti[3])) {
            int k = 3;
            while (k > 0 && (v < tv[k - 1] || (v == tv[k - 1] && n < ti[k - 1]))) {
                tv[k] = tv[k - 1]; ti[k] = ti[k - 1]; k--;
            }
            tv[k] = v; ti[k] = n;
        }
    }
#pragma unroll
    for (int k = 0; k < 4; k++) { s4v[tid][k] = tv[k]; s4i[tid][k] = ti[k]; }
    __syncthreads();

    for (int s = 256; s > 0; s >>= 1) {
        if (tid < s) {
            float av[4], bv[4], ov[4];
            int ai[4], bi[4], oi[4];
#pragma unroll
            for (int k = 0; k < 4; k++) {
                av[k] = s4v[tid][k];     ai[k] = s4i[tid][k];
                bv[k] = s4v[tid + s][k]; bi[k] = s4i[tid + s][k];
            }
            int a = 0, c = 0;
#pragma unroll
            for (int k = 0; k < 4; k++) {
                bool takeA = (av[a] < bv[c]) || (av[a] == bv[c] && ai[a] < bi[c]);
                if (takeA) { ov[k] = av[a]; oi[k] = ai[a]; a++; }
                else       { ov[k] = bv[c]; oi[k] = bi[c]; c++; }
            }
#pragma unroll
            for (int k = 0; k < 4; k++) { s4v[tid][k] = ov[k]; s4i[tid][k] = oi[k]; }
        }
        __syncthreads();
    }
    if (tid < RHEADS) g_idx[b * RHEADS + tid] = s4i[0][tid];
}

/* ------------------- final mem copy-out + readvec(SEQ-1) --------------------- */
__global__ void k_memcopy_rv(float* __restrict__ out_mem) {
    int b  = blockIdx.y;
    int n0 = blockIdx.x * RPB;
    int tid = threadIdx.x;
    int warp = tid >> 5, lane = tid & 31;
    __shared__ float srw[RHEADS][RPB];
    __shared__ float sacc[8][QW];

    for (int l = tid; l < RHEADS * RPB; l += 256) {
        int r = l / RPB, nn = l % RPB;
        srw[r][nn] = g_rw[((size_t)b * RHEADS + r) * NSLOT + n0 + nn];
    }
    __syncthreads();

    float rva[RHEADS][4];
#pragma unroll
    for (int r = 0; r < RHEADS; r++)
#pragma unroll
        for (int c = 0; c < 4; c++) rva[r][c] = 0.f;

    for (int row = warp; row < RPB; row += 8) {
        int n = n0 + row;
        size_t off = ((size_t)b * NSLOT + n) * MDIM + lane * 4;
        float4 v = *reinterpret_cast<const float4*>(&g_mem[off]);
        *reinterpret_cast<float4*>(&out_mem[off]) = v;
        const float* vv = (const float*)&v;
#pragma unroll
        for (int r = 0; r < RHEADS; r++) {
            float w = srw[r][row];
#pragma unroll
            for (int c = 0; c < 4; c++) rva[r][c] += w * vv[c];
        }
    }
#pragma unroll
    for (int r = 0; r < RHEADS; r++)
#pragma unroll
        for (int c = 0; c < 4; c++) sacc[warp][r * MDIM + lane * 4 + c] = rva[r][c];
    __syncthreads();
    for (int l = tid; l < QW; l += 256) {
        float s = 0.f;
#pragma unroll
        for (int w = 0; w < 8; w++) s += sacc[w][l];
        g_rvpart[(((size_t)(SEQ - 1) * RVCH + blockIdx.x) * BS + b) * QW + l] = s;
    }
}

/* ------------------- final projection + softmax ------------------------------ */
__global__ void k_final(const float* __restrict__ Wf, const float* __restrict__ bf,
                        float* __restrict__ out) {
    extern __shared__ float sm[];
    float (*svv)[OUTW] = (float (*)[OUTW])sm;
    float* red = sm + 16 * OUTW;
    int tid = threadIdx.x;
    int r0 = blockIdx.x * 16;
    int t  = r0 / BS;
    int b0 = r0 % BS;

    for (int l = tid; l < 16 * H; l += 128) {
        int rr = l >> 9, k = l & 511;
        svv[rr][k] = g_hist_h[((size_t)(r0 + rr)) * H + k];
    }
    for (int l = tid; l < 16 * QW; l += 128) {
        int rr = l >> 9, k = l & 511;
        float s = 0.f;
#pragma unroll
        for (int c = 0; c < RVCH; c++)
            s += g_rvpart[(((size_t)t * RVCH + c) * BS + (b0 + rr)) * QW + k];
        svv[rr][H + k] = s;
    }
    __syncthreads();

    int half = tid >> 6, col = tid & 63;
    float accs[8];
#pragma unroll
    for (int rr = 0; rr < 8; rr++) accs[rr] = bf[col];
    for (int k = 0; k < OUTW; k++) {
        float w = Wf[(size_t)k * OUTD + col];
#pragma unroll
        for (int rr = 0; rr < 8; rr++) accs[rr] += svv[half * 8 + rr][k] * w;
    }
    for (int rr = 0; rr < 8; rr++) {
        red[tid] = accs[rr];
        __syncthreads();
        for (int s = 32; s > 0; s >>= 1) {
            if ((tid & 63) < s) red[tid] = fmaxf(red[tid], red[tid + s]);
            __syncthreads();
        }
        float mx = red[half * 64];
        __syncthreads();
        float e = expf(accs[rr] - mx);
        red[tid] = e;
        __syncthreads();
        for (int s = 32; s > 0; s >>= 1) {
            if ((tid & 63) < s) red[tid] += red[tid + s];
            __syncthreads();
        }
        float denom = red[half * 64];
        __syncthreads();
        int b = b0 + half * 8 + rr;
        out[((size_t)b * SEQ + t) * OUTD + col] = e / denom;
    }
}

/* ------------------- host: two-stream fork/join pipeline --------------------- */
extern "C" void kernel_launch(void* const* d_in, const int* in_sizes, int n_in,
                              void* d_out, int out_size) {
    const float* x            = (const float*)d_in[0];
    const float* y            = (const float*)d_in[1];
    const float* memory       = (const float*)d_in[2];
    const float* read_weight  = (const float*)d_in[3];
    const float* usage_weight = (const float*)d_in[4];
    const float* Wl           = (const float*)d_in[5];
    const float* bl           = (const float*)d_in[6];
    const float* Wm           = (const float*)d_in[7];
    const float* bm           = (const float*)d_in[8];
    const float* Wf           = (const float*)d_in[9];
    const float* bf           = (const float*)d_in[10];
    const float* alpha        = (const float*)d_in[11];
    float* out = (float*)d_out;

    static cudaStream_t s1;
    static cudaEvent_t evFork, evJoin, evQ[SEQ];
    static int inited = 0;
    if (!inited) {
        cudaStreamCreateWithFlags(&s1, cudaStreamNonBlocking);
        cudaEventCreateWithFlags(&evFork, cudaEventDisableTiming);
        cudaEventCreateWithFlags(&evJoin, cudaEventDisableTiming);
        for (int t = 0; t < SEQ; t++)
            cudaEventCreateWithFlags(&evQ[t], cudaEventDisableTiming);
        cudaFuncSetAttribute(k_final, cudaFuncAttributeMaxDynamicSharedMemorySize,
                             (16 * OUTW + 128) * (int)sizeof(float));
        inited = 1;
    }

    cudaMemcpyToSymbolAsync(g_mem, memory, sizeof(float) * (size_t)BS * NSLOT * MDIM, 0,
                            cudaMemcpyDeviceToDevice, 0);
    cudaMemcpyToSymbolAsync(g_rw, read_weight, sizeof(float) * BS * RHEADS * NSLOT, 0,
                            cudaMemcpyDeviceToDevice, 0);
    cudaMemcpyToSymbolAsync(g_uw, usage_weight, sizeof(float) * BS * NSLOT, 0,
                            cudaMemcpyDeviceToDevice, 0);
    k_init<<<(BS * H + 255) / 256, 256>>>(alpha);
    k_select0<<<BS, 256>>>();

    cudaEventRecord(evFork, 0);
    cudaStreamWaitEvent(s1, evFork, 0);

    /* controller chain on s1 */
    k_zx<<<dim3(32, 1), 256, 0, s1>>>(x, y, Wl, bl, 0);
    k_rec<<<dim3(32, KSPL), 256, 0, s1>>>(Wl);
    k_gates<<<(BS * H) / 256, 256, 0, s1>>>(0);
    k_query<<<dim3(8, KSPL), 256, 0, s1>>>(Wm);
    k_qcomb<<<(BS * QW + 255) / 256, 256, 0, s1>>>(bm, 0);
    cudaEventRecord(evQ[0], s1);
    k_zx<<<dim3(32, SEQ - 1), 256, 0, s1>>>(x, y, Wl, bl, 1);
    for (int t = 1; t < SEQ; t++) {
        k_rec<<<dim3(32, KSPL), 256, 0, s1>>>(Wl);
        k_gates<<<(BS * H) / 256, 256, 0, s1>>>(t);
        k_query<<<dim3(8, KSPL), 256, 0, s1>>>(Wm);
        k_qcomb<<<(BS * QW + 255) / 256, 256, 0, s1>>>(bm, t);
        cudaEventRecord(evQ[t], s1);
    }
    cudaEventRecord(evJoin, s1);

    /* memory chain on capture stream */
    for (int t = 0; t < SEQ; t++) {
        cudaStreamWaitEvent(0, evQ[t], 0);
        k_memupd<<<dim3(RVCH, BS), 256>>>(t);
        k_softmax_uw_sel<<<BS, 512>>>();
    }
    cudaStreamWaitEvent(0, evJoin, 0);

    size_t np = (size_t)BS * SEQ * OUTD;
    size_t nm = (size_t)BS * NSLOT * MDIM;
    size_t nr = (size_t)BS * RHEADS * NSLOT;
    k_memcopy_rv<<<dim3(RVCH, BS), 256>>>(out + np);
    cudaMemcpyFromSymbolAsync(out + np + nm, g_rw, nr * sizeof(float), 0,
                              cudaMemcpyDeviceToDevice, 0);
    cudaMemcpyFromSymbolAsync(out + np + nm + nr, g_uw, (size_t)BS * NSLOT * sizeof(float), 0,
                              cudaMemcpyDeviceToDevice, 0);
    k_final<<<SEQ * BS / 16, 128, (16 * OUTW + 128) * sizeof(float)>>>(Wf, bf, out);
}